// round 7
// baseline (speedup 1.0000x reference)
#include <cuda_runtime.h>
#include <cuda_fp16.h>
#include <math.h>
#include <cstdint>

#define NU 100000
#define NTOT 150000
#define DD 64
#define EE 1250000
#define SS 400000
#define TAU 0.2f
#define EDGE_BIAS 0.5f
#define SCAN_B 586   // ceil(NTOT/256)

typedef unsigned long long ull;

// ---- static scratch (no allocations allowed) ----
__device__ float  g_ego[NTOT * DD];
__device__ float  g_l1[NTOT * 2 * DD];   // [0:NTOT*64) orig chain, [NTOT*64:) masked chain
__device__ float  g_l2[NTOT * 2 * DD];
__device__ float  g_masked[EE];
__device__ int    g_csr_col[EE];
__device__ float2 g_csr_vals2[EE];       // {val, masked_val}
__device__ int    g_counts[NTOT];
__device__ int    g_fillpos[NTOT];
__device__ int    g_rowptr[NTOT + 1];
__device__ int    g_bsum[1024];
__device__ int    g_lastS[EE];
__device__ double g_gate_sum;

// ================= helpers =================
__device__ __forceinline__ uint32_t smem_u32(const void* p) {
    uint32_t a;
    asm("{ .reg .u64 t; cvta.to.shared.u64 t, %1; cvt.u32.u64 %0, t; }" : "=r"(a) : "l"(p));
    return a;
}
__device__ __forceinline__ uint32_t pack_f16x2(float lo, float hi) {
    uint32_t r;
    asm("cvt.rn.f16x2.f32 %0, %1, %2;" : "=r"(r) : "f"(hi), "f"(lo));
    return r;
}
__device__ __forceinline__ void ldsm_x4(uint32_t (&r)[4], uint32_t addr) {
    asm volatile("ldmatrix.sync.aligned.m8n8.x4.shared.b16 {%0,%1,%2,%3}, [%4];"
        : "=r"(r[0]), "=r"(r[1]), "=r"(r[2]), "=r"(r[3]) : "r"(addr));
}
__device__ __forceinline__ void ldsm_x4t(uint32_t (&r)[4], uint32_t addr) {
    asm volatile("ldmatrix.sync.aligned.m8n8.x4.trans.shared.b16 {%0,%1,%2,%3}, [%4];"
        : "=r"(r[0]), "=r"(r[1]), "=r"(r[2]), "=r"(r[3]) : "r"(addr));
}
__device__ __forceinline__ void mma_f16(float (&c)[4], const uint32_t (&a)[4],
                                        uint32_t b0, uint32_t b1) {
    asm volatile(
        "mma.sync.aligned.m16n8k16.row.col.f32.f16.f16.f32 "
        "{%0,%1,%2,%3}, {%4,%5,%6,%7}, {%8,%9}, {%0,%1,%2,%3};"
        : "+f"(c[0]), "+f"(c[1]), "+f"(c[2]), "+f"(c[3])
        : "r"(a[0]), "r"(a[1]), "r"(a[2]), "r"(a[3]), "r"(b0), "r"(b1));
}

// ------------------------------------------------------------------
// 1) per-edge init
// ------------------------------------------------------------------
__global__ void k_init_edges(const float* __restrict__ vals) {
    int i = blockIdx.x * blockDim.x + threadIdx.x;
    if (i < EE) { g_masked[i] = vals[i]; g_lastS[i] = 0; }
    if (i < NTOT) { g_counts[i] = 0; g_fillpos[i] = 0; }
    if (i == 0) g_gate_sum = 0.0;
}

// ------------------------------------------------------------------
// 2) ego = concat(user, item)
// ------------------------------------------------------------------
__global__ void k_init_ego(const float* __restrict__ user,
                           const float* __restrict__ item) {
    int i = blockIdx.x * blockDim.x + threadIdx.x;
    if (i >= NTOT * DD) return;
    g_ego[i] = (i < NU * DD) ? user[i] : item[i - NU * DD];
}

// ------------------------------------------------------------------
// 3) last-writer-wins marker
// ------------------------------------------------------------------
__global__ void k_lastS(const int* __restrict__ sidx) {
    int s = blockIdx.x * blockDim.x + threadIdx.x;
    if (s >= SS) return;
    atomicMax(&g_lastS[sidx[s]], s);
}

// ------------------------------------------------------------------
// 4) gate MLP via fp16 mma.sync, single pass.
//    Block = 128 edges, 256 threads (8 warps; warp w -> edge rows 16w..16w+15).
//    A[128e][128k] fp16 (stride 136 halfs), B[128k][64h] fp16 (stride 72 halfs).
// ------------------------------------------------------------------
#define TE 128
#define A_STRIDE 136
#define B_STRIDE 72
#define A_TILE_B (128 * A_STRIDE * 2)          // 34816
#define B_TILE_B (128 * B_STRIDE * 2)          // 18432
#define GATE_DYN (A_TILE_B + B_TILE_B)         // 53248

__global__ void __launch_bounds__(256)
k_gate_mma(const int* __restrict__ rows, const int* __restrict__ cols,
           const float* __restrict__ vals, const int* __restrict__ sidx,
           const float* __restrict__ eps,
           const float* __restrict__ W1, const float* __restrict__ b1,
           const float* __restrict__ W2, const float* __restrict__ b2) {
    extern __shared__ char dsm[];
    const uint32_t A0 = smem_u32(dsm);
    const uint32_t B0 = A0 + A_TILE_B;

    __shared__ float  b1s[64], W2s[64];
    __shared__ int    eidx[TE];
    __shared__ double gpart[8];

    const int tid  = threadIdx.x;
    const int wid  = tid >> 5;
    const int lane = tid & 31;
    const int base = blockIdx.x * TE;

    if (tid < 64) { b1s[tid] = b1[tid]; W2s[tid] = W2[tid]; }

    // ---- stage B = W1 [128k][64h] fp16, 2 cols per thread ----
    for (int i = tid; i < 4096; i += 256) {
        int k = i >> 5, nn = (i & 31) * 2;
        float v0 = __ldg(&W1[k * 64 + nn]);
        float v1 = __ldg(&W1[k * 64 + nn + 1]);
        *(uint32_t*)(dsm + A_TILE_B + (uint32_t)(k * B_STRIDE + nn) * 2u) =
            pack_f16x2(v0, v1);
    }

    // ---- stage A = cat(ego[su], ego[sv]) fp16 : 2 threads/edge ----
    {
        int e = tid >> 1, p = tid & 1;
        int s = base + e;
        int idx = __ldg(&sidx[s]);
        if (p == 0) eidx[e] = idx;
        int node = p ? __ldg(&cols[idx]) : __ldg(&rows[idx]);
        const float4* src = (const float4*)(g_ego + node * DD);
        uint32_t rowoff = (uint32_t)(e * A_STRIDE + p * DD) * 2u;
#pragma unroll
        for (int j = 0; j < 16; j++) {
            float4 v = __ldg(&src[j]);
            *(uint2*)(dsm + rowoff + (uint32_t)j * 8u) =
                make_uint2(pack_f16x2(v.x, v.y), pack_f16x2(v.z, v.w));
        }
    }
    __syncthreads();

    // ---- mainloop: 8 k-steps, 4 n16-blocks ----
    float C[8][4];
#pragma unroll
    for (int n = 0; n < 8; n++)
#pragma unroll
        for (int q = 0; q < 4; q++) C[n][q] = 0.f;

    const uint32_t a_lane_off =
        (uint32_t)((wid * 16 + (lane & 15)) * A_STRIDE + (lane >> 4) * 8) * 2u;
    const int bg  = lane >> 3;        // ldsm group 0..3
    const int br  = lane & 7;
    const int b_krow_off = (bg & 1) * 8 + br;   // row within k16
    const int b_ncol_off = (bg >> 1) * 8;       // col within n16

#pragma unroll
    for (int k = 0; k < 8; k++) {
        uint32_t a[4];
        ldsm_x4(a, A0 + a_lane_off + (uint32_t)(k * 16 * 2));
        uint32_t b_base = B0 +
            (uint32_t)((k * 16 + b_krow_off) * B_STRIDE + b_ncol_off) * 2u;
#pragma unroll
        for (int nb = 0; nb < 4; nb++) {
            uint32_t b[4];
            ldsm_x4t(b, b_base + (uint32_t)(nb * 16 * 2));
            mma_f16(C[2 * nb],     a, b[0], b[1]);
            mma_f16(C[2 * nb + 1], a, b[2], b[3]);
        }
    }

    // ---- epilogue: logit = relu(C + b1) @ W2 + b2 ----
    const int qr = lane >> 2;
    const int qc = (lane & 3) * 2;
    float pl = 0.f, ph = 0.f;
#pragma unroll
    for (int n = 0; n < 8; n++) {
        int c0 = n * 8 + qc, c1 = c0 + 1;
        pl += fmaxf(C[n][0] + b1s[c0], 0.f) * W2s[c0]
            + fmaxf(C[n][1] + b1s[c1], 0.f) * W2s[c1];
        ph += fmaxf(C[n][2] + b1s[c0], 0.f) * W2s[c0]
            + fmaxf(C[n][3] + b1s[c1], 0.f) * W2s[c1];
    }
    pl += __shfl_xor_sync(0xffffffffu, pl, 1);
    pl += __shfl_xor_sync(0xffffffffu, pl, 2);
    ph += __shfl_xor_sync(0xffffffffu, ph, 1);
    ph += __shfl_xor_sync(0xffffffffu, ph, 2);

    double gsum = 0.0;
    if ((lane & 3) == 0) {
        float b2v = __ldg(b2);
        float logit[2] = {pl + b2v, ph + b2v};
#pragma unroll
        for (int h = 0; h < 2; h++) {
            int e = wid * 16 + qr + h * 8;
            int s = base + e;
            float ee = __ldg(&eps[s]) * (1.f - 2e-6f) + 1e-6f;
            float gumbel = logf(ee) - log1pf(-ee);
            float gate = 1.f / (1.f + expf(-(logit[h] + gumbel) / TAU)) + EDGE_BIAS;
            gsum += (double)gate;
            int idx = eidx[e];
            if (g_lastS[idx] == s) g_masked[idx] = vals[idx] * gate;
        }
    }
#pragma unroll
    for (int off = 16; off; off >>= 1)
        gsum += __shfl_xor_sync(0xffffffffu, gsum, off);
    if (lane == 0) gpart[wid] = gsum;
    __syncthreads();
    if (tid == 0) {
        double t = 0.0;
#pragma unroll
        for (int i = 0; i < 8; i++) t += gpart[i];
        atomicAdd(&g_gate_sum, t);
    }
}

// ------------------------------------------------------------------
// 5) CSR build: count + 3-phase scan + fill
// ------------------------------------------------------------------
__global__ void k_count(const int* __restrict__ rows) {
    int e = blockIdx.x * blockDim.x + threadIdx.x;
    if (e >= EE) return;
    atomicAdd(&g_counts[rows[e]], 1);
}

__global__ void k_scan1() {
    __shared__ int sh[256];
    int i = blockIdx.x * 256 + threadIdx.x;
    int v = (i < NTOT) ? g_counts[i] : 0;
    sh[threadIdx.x] = v;
    __syncthreads();
    for (int off = 128; off; off >>= 1) {
        if (threadIdx.x < off) sh[threadIdx.x] += sh[threadIdx.x + off];
        __syncthreads();
    }
    if (threadIdx.x == 0) g_bsum[blockIdx.x] = sh[0];
}

__global__ void k_scan2() {
    __shared__ int sh[1024];
    int t = threadIdx.x;
    int v = (t < SCAN_B) ? g_bsum[t] : 0;
    sh[t] = v;
    __syncthreads();
    for (int off = 1; off < 1024; off <<= 1) {
        int u = (t >= off) ? sh[t - off] : 0;
        __syncthreads();
        sh[t] += u;
        __syncthreads();
    }
    if (t < SCAN_B) g_bsum[t] = sh[t] - v;  // exclusive
}

__global__ void k_scan3() {
    __shared__ int sh[256];
    int i = blockIdx.x * 256 + threadIdx.x;
    int v = (i < NTOT) ? g_counts[i] : 0;
    sh[threadIdx.x] = v;
    __syncthreads();
    for (int off = 1; off < 256; off <<= 1) {
        int u = (threadIdx.x >= off) ? sh[threadIdx.x - off] : 0;
        __syncthreads();
        sh[threadIdx.x] += u;
        __syncthreads();
    }
    if (i < NTOT) g_rowptr[i] = g_bsum[blockIdx.x] + sh[threadIdx.x] - v;
    if (i == 0) g_rowptr[NTOT] = EE;
}

__global__ void k_fill(const int* __restrict__ rows, const int* __restrict__ cols,
                       const float* __restrict__ vals) {
    int e = blockIdx.x * blockDim.x + threadIdx.x;
    if (e >= EE) return;
    int r = rows[e];
    int slot = g_rowptr[r] + atomicAdd(&g_fillpos[r], 1);
    g_csr_col[slot] = cols[e];
    g_csr_vals2[slot] = make_float2(vals[e], g_masked[e]);
}

// ------------------------------------------------------------------
// 6) SPMM layer 1: fused (both chains gather ego once), outputs split
// ------------------------------------------------------------------
__device__ __forceinline__ void fma2v(float2& a, float v, float2 x) {
    a.x = fmaf(v, x.x, a.x); a.y = fmaf(v, x.y, a.y);
}

__global__ void k_spmm_l1() {
    int warp = (blockIdx.x * blockDim.x + threadIdx.x) >> 5;
    int lane = threadIdx.x & 31;
    if (warp >= NTOT) return;
    int s0 = __ldg(&g_rowptr[warp]);
    int s1 = __ldg(&g_rowptr[warp + 1]);
    const float2* X = (const float2*)g_ego;
    float2 aa = make_float2(0.f, 0.f), ab = make_float2(0.f, 0.f);
    int s = s0;
    for (; s + 4 <= s1; s += 4) {
        int c0 = __ldg(&g_csr_col[s]),     c1 = __ldg(&g_csr_col[s + 1]);
        int c2 = __ldg(&g_csr_col[s + 2]), c3 = __ldg(&g_csr_col[s + 3]);
        float2 v0 = __ldg(&g_csr_vals2[s]),     v1 = __ldg(&g_csr_vals2[s + 1]);
        float2 v2 = __ldg(&g_csr_vals2[s + 2]), v3 = __ldg(&g_csr_vals2[s + 3]);
        float2 x0 = __ldg(&X[c0 * 32 + lane]);
        float2 x1 = __ldg(&X[c1 * 32 + lane]);
        float2 x2 = __ldg(&X[c2 * 32 + lane]);
        float2 x3 = __ldg(&X[c3 * 32 + lane]);
        fma2v(aa, v0.x, x0); fma2v(ab, v0.y, x0);
        fma2v(aa, v1.x, x1); fma2v(ab, v1.y, x1);
        fma2v(aa, v2.x, x2); fma2v(ab, v2.y, x2);
        fma2v(aa, v3.x, x3); fma2v(ab, v3.y, x3);
    }
    for (; s < s1; s++) {
        int c = __ldg(&g_csr_col[s]);
        float2 v = __ldg(&g_csr_vals2[s]);
        float2 x = __ldg(&X[c * 32 + lane]);
        fma2v(aa, v.x, x); fma2v(ab, v.y, x);
    }
    float2* L1o = (float2*)g_l1;
    float2* L1m = (float2*)g_l1 + NTOT * 32;
    L1o[warp * 32 + lane] = aa;
    L1m[warp * 32 + lane] = ab;
}

// ------------------------------------------------------------------
// 7) SPMM middle layer, single chain (L2-resident 38.4MB gather source)
// ------------------------------------------------------------------
__global__ void k_spmm_mid(const float2* __restrict__ X, float2* __restrict__ Y,
                           int comp) {
    int warp = (blockIdx.x * blockDim.x + threadIdx.x) >> 5;
    int lane = threadIdx.x & 31;
    if (warp >= NTOT) return;
    int s0 = __ldg(&g_rowptr[warp]);
    int s1 = __ldg(&g_rowptr[warp + 1]);
    const float* V = (const float*)g_csr_vals2 + comp;
    float2 acc = make_float2(0.f, 0.f);
    int s = s0;
    for (; s + 4 <= s1; s += 4) {
        int c0 = __ldg(&g_csr_col[s]),     c1 = __ldg(&g_csr_col[s + 1]);
        int c2 = __ldg(&g_csr_col[s + 2]), c3 = __ldg(&g_csr_col[s + 3]);
        float v0 = __ldg(&V[2 * s]),       v1 = __ldg(&V[2 * (s + 1)]);
        float v2 = __ldg(&V[2 * (s + 2)]), v3 = __ldg(&V[2 * (s + 3)]);
        float2 x0 = __ldg(&X[c0 * 32 + lane]);
        float2 x1 = __ldg(&X[c1 * 32 + lane]);
        float2 x2 = __ldg(&X[c2 * 32 + lane]);
        float2 x3 = __ldg(&X[c3 * 32 + lane]);
        fma2v(acc, v0, x0); fma2v(acc, v1, x1);
        fma2v(acc, v2, x2); fma2v(acc, v3, x3);
    }
    for (; s < s1; s++) {
        int c = __ldg(&g_csr_col[s]);
        float v = __ldg(&V[2 * s]);
        float2 x = __ldg(&X[c * 32 + lane]);
        fma2v(acc, v, x);
    }
    Y[warp * 32 + lane] = acc;
}

// ------------------------------------------------------------------
// 8) SPMM last layer, single chain, fused mean epilogue
// ------------------------------------------------------------------
__global__ void k_spmm_last(const float2* __restrict__ X,
                            const float2* __restrict__ L1c,
                            float* __restrict__ outc, int comp) {
    int warp = (blockIdx.x * blockDim.x + threadIdx.x) >> 5;
    int lane = threadIdx.x & 31;
    if (warp >= NTOT) return;
    int s0 = __ldg(&g_rowptr[warp]);
    int s1 = __ldg(&g_rowptr[warp + 1]);
    const float* V = (const float*)g_csr_vals2 + comp;
    float2 acc = make_float2(0.f, 0.f);
    int s = s0;
    for (; s + 4 <= s1; s += 4) {
        int c0 = __ldg(&g_csr_col[s]),     c1 = __ldg(&g_csr_col[s + 1]);
        int c2 = __ldg(&g_csr_col[s + 2]), c3 = __ldg(&g_csr_col[s + 3]);
        float v0 = __ldg(&V[2 * s]),       v1 = __ldg(&V[2 * (s + 1)]);
        float v2 = __ldg(&V[2 * (s + 2)]), v3 = __ldg(&V[2 * (s + 3)]);
        float2 x0 = __ldg(&X[c0 * 32 + lane]);
        float2 x1 = __ldg(&X[c1 * 32 + lane]);
        float2 x2 = __ldg(&X[c2 * 32 + lane]);
        float2 x3 = __ldg(&X[c3 * 32 + lane]);
        fma2v(acc, v0, x0); fma2v(acc, v1, x1);
        fma2v(acc, v2, x2); fma2v(acc, v3, x3);
    }
    for (; s < s1; s++) {
        int c = __ldg(&g_csr_col[s]);
        float v = __ldg(&V[2 * s]);
        float2 x = __ldg(&X[c * 32 + lane]);
        fma2v(acc, v, x);
    }
    const float2* E = (const float2*)g_ego;
    float2 e  = __ldg(&E[warp * 32 + lane]);
    float2 p1 = __ldg(&L1c[warp * 32 + lane]);
    float2 p2 = __ldg(&X[warp * 32 + lane]);    // l2 of this chain
    ((float2*)outc)[warp * 32 + lane] =
        make_float2((e.x + p1.x + p2.x + acc.x) * 0.25f,
                    (e.y + p1.y + p2.y + acc.y) * 0.25f);
}

// ------------------------------------------------------------------
// 9) gate mean
// ------------------------------------------------------------------
__global__ void k_final(float* __restrict__ out) {
    out[2 * NTOT * DD] = (float)(g_gate_sum / (double)SS);
}

extern "C" void kernel_launch(void* const* d_in, const int* in_sizes, int n_in,
                              void* d_out, int out_size) {
    const float* user = (const float*)d_in[0];
    const float* item = (const float*)d_in[1];
    const int*   rows = (const int*)d_in[2];
    const int*   cols = (const int*)d_in[3];
    const float* vals = (const float*)d_in[4];
    const int*   sidx = (const int*)d_in[5];
    const float* eps  = (const float*)d_in[6];
    const float* W1   = (const float*)d_in[7];
    const float* b1   = (const float*)d_in[8];
    const float* W2   = (const float*)d_in[9];
    const float* b2   = (const float*)d_in[10];
    float* out = (float*)d_out;

    static int smem_set = 0;
    if (!smem_set) {
        cudaFuncSetAttribute(k_gate_mma,
                             cudaFuncAttributeMaxDynamicSharedMemorySize, GATE_DYN);
        smem_set = 1;
    }

    float* l1; float* l2;
    cudaGetSymbolAddress((void**)&l1, g_l1);
    cudaGetSymbolAddress((void**)&l2, g_l2);
    const float2* L1o = (const float2*)l1;
    const float2* L1m = (const float2*)l1 + NTOT * 32;
    float2* L2o = (float2*)l2;
    float2* L2m = (float2*)l2 + NTOT * 32;

    const int TB = 256;
    k_init_edges<<<(EE + TB - 1) / TB, TB>>>(vals);
    k_init_ego<<<(NTOT * DD + TB - 1) / TB, TB>>>(user, item);
    k_lastS<<<(SS + TB - 1) / TB, TB>>>(sidx);
    k_gate_mma<<<SS / TE, 256, GATE_DYN>>>(rows, cols, vals, sidx, eps, W1, b1, W2, b2);
    k_count<<<(EE + TB - 1) / TB, TB>>>(rows);
    k_scan1<<<SCAN_B, 256>>>();
    k_scan2<<<1, 1024>>>();
    k_scan3<<<SCAN_B, 256>>>();
    k_fill<<<(EE + TB - 1) / TB, TB>>>(rows, cols, vals);

    const int SPMM_BLOCKS = (NTOT * 32 + TB - 1) / TB;
    k_spmm_l1<<<SPMM_BLOCKS, TB>>>();
    k_spmm_mid<<<SPMM_BLOCKS, TB>>>(L1o, L2o, 0);
    k_spmm_mid<<<SPMM_BLOCKS, TB>>>(L1m, L2m, 1);
    k_spmm_last<<<SPMM_BLOCKS, TB>>>((const float2*)L2o, L1o, out, 0);
    k_spmm_last<<<SPMM_BLOCKS, TB>>>((const float2*)L2m, L1m, out + NTOT * DD, 1);

    k_final<<<1, 1>>>(out);
}

// round 8
// speedup vs baseline: 1.1326x; 1.1326x over previous
#include <cuda_runtime.h>
#include <cuda_fp16.h>
#include <math.h>
#include <cstdint>

#define NU 100000
#define NTOT 150000
#define DD 64
#define EE 1250000
#define SS 400000
#define TAU 0.2f
#define EDGE_BIAS 0.5f
#define SCAN_B 586   // ceil(NTOT/256)

typedef unsigned long long ull;

// ---- static scratch (no allocations allowed) ----
__device__ float  g_ego[NTOT * DD];
__device__ float  g_l1[NTOT * 2 * DD];   // interleaved: [row][0:64)=orig, [64:128)=masked
__device__ float  g_l2[NTOT * 2 * DD];
__device__ float  g_masked[EE];
__device__ int    g_csr_col[EE];
__device__ float2 g_csr_vals2[EE];       // {val, masked_val}
__device__ int    g_counts[NTOT];
__device__ int    g_fillpos[NTOT];
__device__ int    g_rowptr[NTOT + 1];
__device__ int    g_bsum[1024];
__device__ int    g_lastS[EE];
__device__ double g_gate_sum;

// ================= helpers =================
__device__ __forceinline__ uint32_t smem_u32(const void* p) {
    uint32_t a;
    asm("{ .reg .u64 t; cvta.to.shared.u64 t, %1; cvt.u32.u64 %0, t; }" : "=r"(a) : "l"(p));
    return a;
}
__device__ __forceinline__ uint32_t pack_f16x2(float lo, float hi) {
    uint32_t r;
    asm("cvt.rn.f16x2.f32 %0, %1, %2;" : "=r"(r) : "f"(hi), "f"(lo));
    return r;
}
__device__ __forceinline__ void ldsm_x4(uint32_t (&r)[4], uint32_t addr) {
    asm volatile("ldmatrix.sync.aligned.m8n8.x4.shared.b16 {%0,%1,%2,%3}, [%4];"
        : "=r"(r[0]), "=r"(r[1]), "=r"(r[2]), "=r"(r[3]) : "r"(addr));
}
__device__ __forceinline__ void ldsm_x4t(uint32_t (&r)[4], uint32_t addr) {
    asm volatile("ldmatrix.sync.aligned.m8n8.x4.trans.shared.b16 {%0,%1,%2,%3}, [%4];"
        : "=r"(r[0]), "=r"(r[1]), "=r"(r[2]), "=r"(r[3]) : "r"(addr));
}
__device__ __forceinline__ void mma_f16(float (&c)[4], const uint32_t (&a)[4],
                                        uint32_t b0, uint32_t b1) {
    asm volatile(
        "mma.sync.aligned.m16n8k16.row.col.f32.f16.f16.f32 "
        "{%0,%1,%2,%3}, {%4,%5,%6,%7}, {%8,%9}, {%0,%1,%2,%3};"
        : "+f"(c[0]), "+f"(c[1]), "+f"(c[2]), "+f"(c[3])
        : "r"(a[0]), "r"(a[1]), "r"(a[2]), "r"(a[3]), "r"(b0), "r"(b1));
}

// ------------------------------------------------------------------
// 1) per-edge init
// ------------------------------------------------------------------
__global__ void k_init_edges(const float* __restrict__ vals) {
    int i = blockIdx.x * blockDim.x + threadIdx.x;
    if (i < EE) { g_masked[i] = vals[i]; g_lastS[i] = 0; }
    if (i < NTOT) { g_counts[i] = 0; g_fillpos[i] = 0; }
    if (i == 0) g_gate_sum = 0.0;
}

// ------------------------------------------------------------------
// 2) ego = concat(user, item)
// ------------------------------------------------------------------
__global__ void k_init_ego(const float* __restrict__ user,
                           const float* __restrict__ item) {
    int i = blockIdx.x * blockDim.x + threadIdx.x;
    if (i >= NTOT * DD) return;
    g_ego[i] = (i < NU * DD) ? user[i] : item[i - NU * DD];
}

// ------------------------------------------------------------------
// 3) last-writer-wins marker
// ------------------------------------------------------------------
__global__ void k_lastS(const int* __restrict__ sidx) {
    int s = blockIdx.x * blockDim.x + threadIdx.x;
    if (s >= SS) return;
    atomicMax(&g_lastS[sidx[s]], s);
}

// ------------------------------------------------------------------
// 4) gate MLP via fp16 mma.sync, single pass (R7 proven, 137us).
// ------------------------------------------------------------------
#define TE 128
#define A_STRIDE 136
#define B_STRIDE 72
#define A_TILE_B (128 * A_STRIDE * 2)          // 34816
#define B_TILE_B (128 * B_STRIDE * 2)          // 18432
#define GATE_DYN (A_TILE_B + B_TILE_B)         // 53248

__global__ void __launch_bounds__(256)
k_gate_mma(const int* __restrict__ rows, const int* __restrict__ cols,
           const float* __restrict__ vals, const int* __restrict__ sidx,
           const float* __restrict__ eps,
           const float* __restrict__ W1, const float* __restrict__ b1,
           const float* __restrict__ W2, const float* __restrict__ b2) {
    extern __shared__ char dsm[];
    const uint32_t A0 = smem_u32(dsm);
    const uint32_t B0 = A0 + A_TILE_B;

    __shared__ float  b1s[64], W2s[64];
    __shared__ int    eidx[TE];
    __shared__ double gpart[8];

    const int tid  = threadIdx.x;
    const int wid  = tid >> 5;
    const int lane = tid & 31;
    const int base = blockIdx.x * TE;

    if (tid < 64) { b1s[tid] = b1[tid]; W2s[tid] = W2[tid]; }

    // ---- stage B = W1 [128k][64h] fp16, 2 cols per thread ----
    for (int i = tid; i < 4096; i += 256) {
        int k = i >> 5, nn = (i & 31) * 2;
        float v0 = __ldg(&W1[k * 64 + nn]);
        float v1 = __ldg(&W1[k * 64 + nn + 1]);
        *(uint32_t*)(dsm + A_TILE_B + (uint32_t)(k * B_STRIDE + nn) * 2u) =
            pack_f16x2(v0, v1);
    }

    // ---- stage A = cat(ego[su], ego[sv]) fp16 : 2 threads/edge ----
    {
        int e = tid >> 1, p = tid & 1;
        int s = base + e;
        int idx = __ldg(&sidx[s]);
        if (p == 0) eidx[e] = idx;
        int node = p ? __ldg(&cols[idx]) : __ldg(&rows[idx]);
        const float4* src = (const float4*)(g_ego + node * DD);
        uint32_t rowoff = (uint32_t)(e * A_STRIDE + p * DD) * 2u;
#pragma unroll
        for (int j = 0; j < 16; j++) {
            float4 v = __ldg(&src[j]);
            *(uint2*)(dsm + rowoff + (uint32_t)j * 8u) =
                make_uint2(pack_f16x2(v.x, v.y), pack_f16x2(v.z, v.w));
        }
    }
    __syncthreads();

    // ---- mainloop: 8 k-steps, 4 n16-blocks ----
    float C[8][4];
#pragma unroll
    for (int n = 0; n < 8; n++)
#pragma unroll
        for (int q = 0; q < 4; q++) C[n][q] = 0.f;

    const uint32_t a_lane_off =
        (uint32_t)((wid * 16 + (lane & 15)) * A_STRIDE + (lane >> 4) * 8) * 2u;
    const int bg  = lane >> 3;
    const int br  = lane & 7;
    const int b_krow_off = (bg & 1) * 8 + br;
    const int b_ncol_off = (bg >> 1) * 8;

#pragma unroll
    for (int k = 0; k < 8; k++) {
        uint32_t a[4];
        ldsm_x4(a, A0 + a_lane_off + (uint32_t)(k * 16 * 2));
        uint32_t b_base = B0 +
            (uint32_t)((k * 16 + b_krow_off) * B_STRIDE + b_ncol_off) * 2u;
#pragma unroll
        for (int nb = 0; nb < 4; nb++) {
            uint32_t b[4];
            ldsm_x4t(b, b_base + (uint32_t)(nb * 16 * 2));
            mma_f16(C[2 * nb],     a, b[0], b[1]);
            mma_f16(C[2 * nb + 1], a, b[2], b[3]);
        }
    }

    // ---- epilogue ----
    const int qr = lane >> 2;
    const int qc = (lane & 3) * 2;
    float pl = 0.f, ph = 0.f;
#pragma unroll
    for (int n = 0; n < 8; n++) {
        int c0 = n * 8 + qc, c1 = c0 + 1;
        pl += fmaxf(C[n][0] + b1s[c0], 0.f) * W2s[c0]
            + fmaxf(C[n][1] + b1s[c1], 0.f) * W2s[c1];
        ph += fmaxf(C[n][2] + b1s[c0], 0.f) * W2s[c0]
            + fmaxf(C[n][3] + b1s[c1], 0.f) * W2s[c1];
    }
    pl += __shfl_xor_sync(0xffffffffu, pl, 1);
    pl += __shfl_xor_sync(0xffffffffu, pl, 2);
    ph += __shfl_xor_sync(0xffffffffu, ph, 1);
    ph += __shfl_xor_sync(0xffffffffu, ph, 2);

    double gsum = 0.0;
    if ((lane & 3) == 0) {
        float b2v = __ldg(b2);
        float logit[2] = {pl + b2v, ph + b2v};
#pragma unroll
        for (int h = 0; h < 2; h++) {
            int e = wid * 16 + qr + h * 8;
            int s = base + e;
            float ee = __ldg(&eps[s]) * (1.f - 2e-6f) + 1e-6f;
            float gumbel = logf(ee) - log1pf(-ee);
            float gate = 1.f / (1.f + expf(-(logit[h] + gumbel) / TAU)) + EDGE_BIAS;
            gsum += (double)gate;
            int idx = eidx[e];
            if (g_lastS[idx] == s) g_masked[idx] = vals[idx] * gate;
        }
    }
#pragma unroll
    for (int off = 16; off; off >>= 1)
        gsum += __shfl_xor_sync(0xffffffffu, gsum, off);
    if (lane == 0) gpart[wid] = gsum;
    __syncthreads();
    if (tid == 0) {
        double t = 0.0;
#pragma unroll
        for (int i = 0; i < 8; i++) t += gpart[i];
        atomicAdd(&g_gate_sum, t);
    }
}

// ------------------------------------------------------------------
// 5) CSR build: count + 3-phase scan + fill
// ------------------------------------------------------------------
__global__ void k_count(const int* __restrict__ rows) {
    int e = blockIdx.x * blockDim.x + threadIdx.x;
    if (e >= EE) return;
    atomicAdd(&g_counts[rows[e]], 1);
}

__global__ void k_scan1() {
    __shared__ int sh[256];
    int i = blockIdx.x * 256 + threadIdx.x;
    int v = (i < NTOT) ? g_counts[i] : 0;
    sh[threadIdx.x] = v;
    __syncthreads();
    for (int off = 128; off; off >>= 1) {
        if (threadIdx.x < off) sh[threadIdx.x] += sh[threadIdx.x + off];
        __syncthreads();
    }
    if (threadIdx.x == 0) g_bsum[blockIdx.x] = sh[0];
}

__global__ void k_scan2() {
    __shared__ int sh[1024];
    int t = threadIdx.x;
    int v = (t < SCAN_B) ? g_bsum[t] : 0;
    sh[t] = v;
    __syncthreads();
    for (int off = 1; off < 1024; off <<= 1) {
        int u = (t >= off) ? sh[t - off] : 0;
        __syncthreads();
        sh[t] += u;
        __syncthreads();
    }
    if (t < SCAN_B) g_bsum[t] = sh[t] - v;  // exclusive
}

__global__ void k_scan3() {
    __shared__ int sh[256];
    int i = blockIdx.x * 256 + threadIdx.x;
    int v = (i < NTOT) ? g_counts[i] : 0;
    sh[threadIdx.x] = v;
    __syncthreads();
    for (int off = 1; off < 256; off <<= 1) {
        int u = (threadIdx.x >= off) ? sh[threadIdx.x - off] : 0;
        __syncthreads();
        sh[threadIdx.x] += u;
        __syncthreads();
    }
    if (i < NTOT) g_rowptr[i] = g_bsum[blockIdx.x] + sh[threadIdx.x] - v;
    if (i == 0) g_rowptr[NTOT] = EE;
}

__global__ void k_fill(const int* __restrict__ rows, const int* __restrict__ cols,
                       const float* __restrict__ vals) {
    int e = blockIdx.x * blockDim.x + threadIdx.x;
    if (e >= EE) return;
    int r = rows[e];
    int slot = g_rowptr[r] + atomicAdd(&g_fillpos[r], 1);
    g_csr_col[slot] = cols[e];
    g_csr_vals2[slot] = make_float2(vals[e], g_masked[e]);
}

// ------------------------------------------------------------------
// 6) SPMM layer 1: both chains gather ego once -> interleaved l1
// ------------------------------------------------------------------
__device__ __forceinline__ void fma2v(float2& a, float v, float2 x) {
    a.x = fmaf(v, x.x, a.x); a.y = fmaf(v, x.y, a.y);
}

__global__ void k_spmm_l1() {
    int warp = (blockIdx.x * blockDim.x + threadIdx.x) >> 5;
    int lane = threadIdx.x & 31;
    if (warp >= NTOT) return;
    int s0 = __ldg(&g_rowptr[warp]);
    int s1 = __ldg(&g_rowptr[warp + 1]);
    const float2* X = (const float2*)g_ego;
    float2 aa = make_float2(0.f, 0.f), ab = make_float2(0.f, 0.f);
    int s = s0;
    for (; s + 4 <= s1; s += 4) {
        int c0 = __ldg(&g_csr_col[s]),     c1 = __ldg(&g_csr_col[s + 1]);
        int c2 = __ldg(&g_csr_col[s + 2]), c3 = __ldg(&g_csr_col[s + 3]);
        float2 v0 = __ldg(&g_csr_vals2[s]),     v1 = __ldg(&g_csr_vals2[s + 1]);
        float2 v2 = __ldg(&g_csr_vals2[s + 2]), v3 = __ldg(&g_csr_vals2[s + 3]);
        float2 x0 = __ldg(&X[c0 * 32 + lane]);
        float2 x1 = __ldg(&X[c1 * 32 + lane]);
        float2 x2 = __ldg(&X[c2 * 32 + lane]);
        float2 x3 = __ldg(&X[c3 * 32 + lane]);
        fma2v(aa, v0.x, x0); fma2v(ab, v0.y, x0);
        fma2v(aa, v1.x, x1); fma2v(ab, v1.y, x1);
        fma2v(aa, v2.x, x2); fma2v(ab, v2.y, x2);
        fma2v(aa, v3.x, x3); fma2v(ab, v3.y, x3);
    }
    for (; s < s1; s++) {
        int c = __ldg(&g_csr_col[s]);
        float2 v = __ldg(&g_csr_vals2[s]);
        float2 x = __ldg(&X[c * 32 + lane]);
        fma2v(aa, v.x, x); fma2v(ab, v.y, x);
    }
    float2* L1 = (float2*)g_l1;
    L1[warp * 64 + lane] = aa;
    L1[warp * 64 + 32 + lane] = ab;
}

// ------------------------------------------------------------------
// 7) SPMM layer 2: interleaved l1 -> interleaved l2
// ------------------------------------------------------------------
__global__ void k_spmm_l2() {
    int warp = (blockIdx.x * blockDim.x + threadIdx.x) >> 5;
    int lane = threadIdx.x & 31;
    if (warp >= NTOT) return;
    int s0 = __ldg(&g_rowptr[warp]);
    int s1 = __ldg(&g_rowptr[warp + 1]);
    const float2* X = (const float2*)g_l1;
    float2 aa = make_float2(0.f, 0.f), ab = make_float2(0.f, 0.f);
    int s = s0;
    for (; s + 2 <= s1; s += 2) {
        int c0 = __ldg(&g_csr_col[s]), c1 = __ldg(&g_csr_col[s + 1]);
        float2 v0 = __ldg(&g_csr_vals2[s]), v1 = __ldg(&g_csr_vals2[s + 1]);
        float2 xa0 = __ldg(&X[c0 * 64 + lane]);
        float2 xb0 = __ldg(&X[c0 * 64 + 32 + lane]);
        float2 xa1 = __ldg(&X[c1 * 64 + lane]);
        float2 xb1 = __ldg(&X[c1 * 64 + 32 + lane]);
        fma2v(aa, v0.x, xa0); fma2v(ab, v0.y, xb0);
        fma2v(aa, v1.x, xa1); fma2v(ab, v1.y, xb1);
    }
    for (; s < s1; s++) {
        int c = __ldg(&g_csr_col[s]);
        float2 v = __ldg(&g_csr_vals2[s]);
        float2 xa = __ldg(&X[c * 64 + lane]);
        float2 xb = __ldg(&X[c * 64 + 32 + lane]);
        fma2v(aa, v.x, xa); fma2v(ab, v.y, xb);
    }
    float2* L2 = (float2*)g_l2;
    L2[warp * 64 + lane] = aa;
    L2[warp * 64 + 32 + lane] = ab;
}

// ------------------------------------------------------------------
// 8) SPMM layer 3 fused with mean: out = (ego + l1 + l2 + l3) / 4
// ------------------------------------------------------------------
__global__ void k_spmm_l3(float* __restrict__ out) {
    int warp = (blockIdx.x * blockDim.x + threadIdx.x) >> 5;
    int lane = threadIdx.x & 31;
    if (warp >= NTOT) return;
    int s0 = __ldg(&g_rowptr[warp]);
    int s1 = __ldg(&g_rowptr[warp + 1]);
    const float2* X = (const float2*)g_l2;
    float2 aa = make_float2(0.f, 0.f), ab = make_float2(0.f, 0.f);
    int s = s0;
    for (; s + 2 <= s1; s += 2) {
        int c0 = __ldg(&g_csr_col[s]), c1 = __ldg(&g_csr_col[s + 1]);
        float2 v0 = __ldg(&g_csr_vals2[s]), v1 = __ldg(&g_csr_vals2[s + 1]);
        float2 xa0 = __ldg(&X[c0 * 64 + lane]);
        float2 xb0 = __ldg(&X[c0 * 64 + 32 + lane]);
        float2 xa1 = __ldg(&X[c1 * 64 + lane]);
        float2 xb1 = __ldg(&X[c1 * 64 + 32 + lane]);
        fma2v(aa, v0.x, xa0); fma2v(ab, v0.y, xb0);
        fma2v(aa, v1.x, xa1); fma2v(ab, v1.y, xb1);
    }
    for (; s < s1; s++) {
        int c = __ldg(&g_csr_col[s]);
        float2 v = __ldg(&g_csr_vals2[s]);
        float2 xa = __ldg(&X[c * 64 + lane]);
        float2 xb = __ldg(&X[c * 64 + 32 + lane]);
        fma2v(aa, v.x, xa); fma2v(ab, v.y, xb);
    }
    const float2* E  = (const float2*)g_ego;
    const float2* L1 = (const float2*)g_l1;
    const float2* L2 = (const float2*)g_l2;
    float2 e  = E[warp * 32 + lane];
    float2 p1 = L1[warp * 64 + lane];
    float2 q1 = L1[warp * 64 + 32 + lane];
    float2 p2 = L2[warp * 64 + lane];
    float2 q2 = L2[warp * 64 + 32 + lane];
    float2* outA = (float2*)out;
    float2* outB = (float2*)out + NTOT * 32;
    outA[warp * 32 + lane] = make_float2((e.x + p1.x + p2.x + aa.x) * 0.25f,
                                         (e.y + p1.y + p2.y + aa.y) * 0.25f);
    outB[warp * 32 + lane] = make_float2((e.x + q1.x + q2.x + ab.x) * 0.25f,
                                         (e.y + q1.y + q2.y + ab.y) * 0.25f);
}

// ------------------------------------------------------------------
// 9) gate mean
// ------------------------------------------------------------------
__global__ void k_final(float* __restrict__ out) {
    out[2 * NTOT * DD] = (float)(g_gate_sum / (double)SS);
}

extern "C" void kernel_launch(void* const* d_in, const int* in_sizes, int n_in,
                              void* d_out, int out_size) {
    const float* user = (const float*)d_in[0];
    const float* item = (const float*)d_in[1];
    const int*   rows = (const int*)d_in[2];
    const int*   cols = (const int*)d_in[3];
    const float* vals = (const float*)d_in[4];
    const int*   sidx = (const int*)d_in[5];
    const float* eps  = (const float*)d_in[6];
    const float* W1   = (const float*)d_in[7];
    const float* b1   = (const float*)d_in[8];
    const float* W2   = (const float*)d_in[9];
    const float* b2   = (const float*)d_in[10];
    float* out = (float*)d_out;

    static int smem_set = 0;
    if (!smem_set) {
        cudaFuncSetAttribute(k_gate_mma,
                             cudaFuncAttributeMaxDynamicSharedMemorySize, GATE_DYN);
        smem_set = 1;
    }

    const int TB = 256;
    k_init_edges<<<(EE + TB - 1) / TB, TB>>>(vals);
    k_init_ego<<<(NTOT * DD + TB - 1) / TB, TB>>>(user, item);
    k_lastS<<<(SS + TB - 1) / TB, TB>>>(sidx);
    k_gate_mma<<<SS / TE, 256, GATE_DYN>>>(rows, cols, vals, sidx, eps, W1, b1, W2, b2);
    k_count<<<(EE + TB - 1) / TB, TB>>>(rows);
    k_scan1<<<SCAN_B, 256>>>();
    k_scan2<<<1, 1024>>>();
    k_scan3<<<SCAN_B, 256>>>();
    k_fill<<<(EE + TB - 1) / TB, TB>>>(rows, cols, vals);

    const int SPMM_BLOCKS = (NTOT * 32 + TB - 1) / TB;
    k_spmm_l1<<<SPMM_BLOCKS, TB>>>();
    k_spmm_l2<<<SPMM_BLOCKS, TB>>>();
    k_spmm_l3<<<SPMM_BLOCKS, TB>>>(out);

    k_final<<<1, 1>>>(out);
}

// round 9
// speedup vs baseline: 1.1880x; 1.0489x over previous
#include <cuda_runtime.h>
#include <cuda_fp16.h>
#include <math.h>
#include <cstdint>

#define NU 100000
#define NTOT 150000
#define DD 64
#define EE 1250000
#define SS 400000
#define TAU 0.2f
#define EDGE_BIAS 0.5f
#define SCAN_B 586   // ceil(NTOT/256)

typedef unsigned long long ull;

// ---- static scratch (no allocations allowed) ----
__device__ float    g_ego[NTOT * DD];
__device__ float    g_l1[NTOT * 2 * DD];   // interleaved: [row][0:64)=orig, [64:128)=masked
__device__ float    g_l2[NTOT * 2 * DD];
__device__ float    g_masked[EE];
__device__ int      g_csr_col[EE];
__device__ float2   g_csr_vals2[EE];       // {val, masked_val}
__device__ int      g_counts[NTOT];
__device__ int      g_fillpos[NTOT];
__device__ int      g_rowptr[NTOT + 1];
__device__ int      g_bsum[1024];
__device__ int      g_lastS[EE];
__device__ uint32_t g_w1h[64 * 64];        // W1 packed fp16x2: [128k][32 pairs]
__device__ double   g_gate_sum;

// ================= helpers =================
__device__ __forceinline__ uint32_t smem_u32(const void* p) {
    uint32_t a;
    asm("{ .reg .u64 t; cvta.to.shared.u64 t, %1; cvt.u32.u64 %0, t; }" : "=r"(a) : "l"(p));
    return a;
}
__device__ __forceinline__ uint32_t pack_f16x2(float lo, float hi) {
    uint32_t r;
    asm("cvt.rn.f16x2.f32 %0, %1, %2;" : "=r"(r) : "f"(hi), "f"(lo));
    return r;
}
__device__ __forceinline__ void ldsm_x4(uint32_t (&r)[4], uint32_t addr) {
    asm volatile("ldmatrix.sync.aligned.m8n8.x4.shared.b16 {%0,%1,%2,%3}, [%4];"
        : "=r"(r[0]), "=r"(r[1]), "=r"(r[2]), "=r"(r[3]) : "r"(addr));
}
__device__ __forceinline__ void ldsm_x4t(uint32_t (&r)[4], uint32_t addr) {
    asm volatile("ldmatrix.sync.aligned.m8n8.x4.trans.shared.b16 {%0,%1,%2,%3}, [%4];"
        : "=r"(r[0]), "=r"(r[1]), "=r"(r[2]), "=r"(r[3]) : "r"(addr));
}
__device__ __forceinline__ void mma_f16(float (&c)[4], const uint32_t (&a)[4],
                                        uint32_t b0, uint32_t b1) {
    asm volatile(
        "mma.sync.aligned.m16n8k16.row.col.f32.f16.f16.f32 "
        "{%0,%1,%2,%3}, {%4,%5,%6,%7}, {%8,%9}, {%0,%1,%2,%3};"
        : "+f"(c[0]), "+f"(c[1]), "+f"(c[2]), "+f"(c[3])
        : "r"(a[0]), "r"(a[1]), "r"(a[2]), "r"(a[3]), "r"(b0), "r"(b1));
}

// ------------------------------------------------------------------
// 1) per-edge init + pack W1 to fp16
// ------------------------------------------------------------------
__global__ void k_init_edges(const float* __restrict__ vals,
                             const float* __restrict__ W1) {
    int i = blockIdx.x * blockDim.x + threadIdx.x;
    if (i < EE) { g_masked[i] = vals[i]; g_lastS[i] = 0; }
    if (i < NTOT) { g_counts[i] = 0; g_fillpos[i] = 0; }
    if (i < 4096) {
        float v0 = W1[2 * i];
        float v1 = W1[2 * i + 1];
        g_w1h[i] = pack_f16x2(v0, v1);
    }
    if (i == 0) g_gate_sum = 0.0;
}

// ------------------------------------------------------------------
// 2) combined: ego copy + degree count + lastS
// ------------------------------------------------------------------
__global__ void k_prep(const float* __restrict__ user,
                       const float* __restrict__ item,
                       const int* __restrict__ rows,
                       const int* __restrict__ sidx) {
    int i = blockIdx.x * blockDim.x + threadIdx.x;
    if (i < NTOT * DD)
        g_ego[i] = (i < NU * DD) ? user[i] : item[i - NU * DD];
    if (i < EE) atomicAdd(&g_counts[rows[i]], 1);
    if (i < SS) atomicMax(&g_lastS[sidx[i]], i);
}

// ------------------------------------------------------------------
// 3) gate MLP via fp16 mma.sync, single pass.
// ------------------------------------------------------------------
#define TE 128
#define A_STRIDE 136
#define B_STRIDE 72
#define A_TILE_B (128 * A_STRIDE * 2)          // 34816
#define B_TILE_B (128 * B_STRIDE * 2)          // 18432
#define GATE_DYN (A_TILE_B + B_TILE_B)         // 53248

__global__ void __launch_bounds__(256)
k_gate_mma(const int* __restrict__ rows, const int* __restrict__ cols,
           const float* __restrict__ vals, const int* __restrict__ sidx,
           const float* __restrict__ eps,
           const float* __restrict__ b1,
           const float* __restrict__ W2, const float* __restrict__ b2) {
    extern __shared__ char dsm[];
    const uint32_t A0 = smem_u32(dsm);
    const uint32_t B0 = A0 + A_TILE_B;

    __shared__ float  b1s[64], W2s[64];
    __shared__ int    eidx[TE];
    __shared__ double gpart[8];

    const int tid  = threadIdx.x;
    const int wid  = tid >> 5;
    const int lane = tid & 31;
    const int base = blockIdx.x * TE;

    if (tid < 64) { b1s[tid] = b1[tid]; W2s[tid] = W2[tid]; }

    // ---- stage B: packed fp16 W1, vectorized 16B copy ----
    // g_w1h layout: [k][nn pair] ; smem row stride B_STRIDE halfs = 36 pairs
    {
        const uint4* src = (const uint4*)g_w1h;     // 1024 uint4
        for (int i = tid; i < 1024; i += 256) {
            int k = i >> 3, c4 = (i & 7) * 4;       // 8 uint4 per k-row
            uint4 v = __ldg(&src[i]);
            *(uint4*)(dsm + A_TILE_B + (uint32_t)(k * B_STRIDE + 2 * c4) * 2u) = v;
        }
    }

    // ---- stage A = cat(ego[su], ego[sv]) fp16 : 2 threads/edge ----
    {
        int e = tid >> 1, p = tid & 1;
        int s = base + e;
        int idx = __ldg(&sidx[s]);
        if (p == 0) eidx[e] = idx;
        int node = p ? __ldg(&cols[idx]) : __ldg(&rows[idx]);
        const float4* src = (const float4*)(g_ego + node * DD);
        uint32_t rowoff = (uint32_t)(e * A_STRIDE + p * DD) * 2u;
#pragma unroll
        for (int j = 0; j < 16; j++) {
            float4 v = __ldg(&src[j]);
            *(uint2*)(dsm + rowoff + (uint32_t)j * 8u) =
                make_uint2(pack_f16x2(v.x, v.y), pack_f16x2(v.z, v.w));
        }
    }
    __syncthreads();

    // ---- mainloop: 8 k-steps, 4 n16-blocks ----
    float C[8][4];
#pragma unroll
    for (int n = 0; n < 8; n++)
#pragma unroll
        for (int q = 0; q < 4; q++) C[n][q] = 0.f;

    const uint32_t a_lane_off =
        (uint32_t)((wid * 16 + (lane & 15)) * A_STRIDE + (lane >> 4) * 8) * 2u;
    const int bg  = lane >> 3;
    const int br  = lane & 7;
    const int b_krow_off = (bg & 1) * 8 + br;
    const int b_ncol_off = (bg >> 1) * 8;

#pragma unroll
    for (int k = 0; k < 8; k++) {
        uint32_t a[4];
        ldsm_x4(a, A0 + a_lane_off + (uint32_t)(k * 16 * 2));
        uint32_t b_base = B0 +
            (uint32_t)((k * 16 + b_krow_off) * B_STRIDE + b_ncol_off) * 2u;
#pragma unroll
        for (int nb = 0; nb < 4; nb++) {
            uint32_t b[4];
            ldsm_x4t(b, b_base + (uint32_t)(nb * 16 * 2));
            mma_f16(C[2 * nb],     a, b[0], b[1]);
            mma_f16(C[2 * nb + 1], a, b[2], b[3]);
        }
    }

    // ---- epilogue ----
    const int qr = lane >> 2;
    const int qc = (lane & 3) * 2;
    float pl = 0.f, ph = 0.f;
#pragma unroll
    for (int n = 0; n < 8; n++) {
        int c0 = n * 8 + qc, c1 = c0 + 1;
        pl += fmaxf(C[n][0] + b1s[c0], 0.f) * W2s[c0]
            + fmaxf(C[n][1] + b1s[c1], 0.f) * W2s[c1];
        ph += fmaxf(C[n][2] + b1s[c0], 0.f) * W2s[c0]
            + fmaxf(C[n][3] + b1s[c1], 0.f) * W2s[c1];
    }
    pl += __shfl_xor_sync(0xffffffffu, pl, 1);
    pl += __shfl_xor_sync(0xffffffffu, pl, 2);
    ph += __shfl_xor_sync(0xffffffffu, ph, 1);
    ph += __shfl_xor_sync(0xffffffffu, ph, 2);

    double gsum = 0.0;
    if ((lane & 3) == 0) {
        float b2v = __ldg(b2);
        float logit[2] = {pl + b2v, ph + b2v};
#pragma unroll
        for (int h = 0; h < 2; h++) {
            int e = wid * 16 + qr + h * 8;
            int s = base + e;
            float ee = __ldg(&eps[s]) * (1.f - 2e-6f) + 1e-6f;
            float gumbel = logf(ee) - log1pf(-ee);
            float gate = 1.f / (1.f + expf(-(logit[h] + gumbel) / TAU)) + EDGE_BIAS;
            gsum += (double)gate;
            int idx = eidx[e];
            if (g_lastS[idx] == s) g_masked[idx] = vals[idx] * gate;
        }
    }
#pragma unroll
    for (int off = 16; off; off >>= 1)
        gsum += __shfl_xor_sync(0xffffffffu, gsum, off);
    if (lane == 0) gpart[wid] = gsum;
    __syncthreads();
    if (tid == 0) {
        double t = 0.0;
#pragma unroll
        for (int i = 0; i < 8; i++) t += gpart[i];
        atomicAdd(&g_gate_sum, t);
    }
}

// ------------------------------------------------------------------
// 4) CSR scan (3-phase) + fill
// ------------------------------------------------------------------
__global__ void k_scan1() {
    __shared__ int sh[256];
    int i = blockIdx.x * 256 + threadIdx.x;
    int v = (i < NTOT) ? g_counts[i] : 0;
    sh[threadIdx.x] = v;
    __syncthreads();
    for (int off = 128; off; off >>= 1) {
        if (threadIdx.x < off) sh[threadIdx.x] += sh[threadIdx.x + off];
        __syncthreads();
    }
    if (threadIdx.x == 0) g_bsum[blockIdx.x] = sh[0];
}

__global__ void k_scan2() {
    __shared__ int sh[1024];
    int t = threadIdx.x;
    int v = (t < SCAN_B) ? g_bsum[t] : 0;
    sh[t] = v;
    __syncthreads();
    for (int off = 1; off < 1024; off <<= 1) {
        int u = (t >= off) ? sh[t - off] : 0;
        __syncthreads();
        sh[t] += u;
        __syncthreads();
    }
    if (t < SCAN_B) g_bsum[t] = sh[t] - v;  // exclusive
}

__global__ void k_scan3() {
    __shared__ int sh[256];
    int i = blockIdx.x * 256 + threadIdx.x;
    int v = (i < NTOT) ? g_counts[i] : 0;
    sh[threadIdx.x] = v;
    __syncthreads();
    for (int off = 1; off < 256; off <<= 1) {
        int u = (threadIdx.x >= off) ? sh[threadIdx.x - off] : 0;
        __syncthreads();
        sh[threadIdx.x] += u;
        __syncthreads();
    }
    if (i < NTOT) g_rowptr[i] = g_bsum[blockIdx.x] + sh[threadIdx.x] - v;
    if (i == 0) g_rowptr[NTOT] = EE;
}

__global__ void k_fill(const int* __restrict__ rows, const int* __restrict__ cols,
                       const float* __restrict__ vals) {
    int e = blockIdx.x * blockDim.x + threadIdx.x;
    if (e >= EE) return;
    int r = rows[e];
    int slot = g_rowptr[r] + atomicAdd(&g_fillpos[r], 1);
    g_csr_col[slot] = cols[e];
    g_csr_vals2[slot] = make_float2(vals[e], g_masked[e]);
}

// ------------------------------------------------------------------
// 5) SPMM layer 1: both chains gather ego once -> interleaved l1
// ------------------------------------------------------------------
__device__ __forceinline__ void fma2v(float2& a, float v, float2 x) {
    a.x = fmaf(v, x.x, a.x); a.y = fmaf(v, x.y, a.y);
}

__global__ void k_spmm_l1() {
    int warp = (blockIdx.x * blockDim.x + threadIdx.x) >> 5;
    int lane = threadIdx.x & 31;
    if (warp >= NTOT) return;
    int s0 = __ldg(&g_rowptr[warp]);
    int s1 = __ldg(&g_rowptr[warp + 1]);
    const float2* X = (const float2*)g_ego;
    float2 aa = make_float2(0.f, 0.f), ab = make_float2(0.f, 0.f);
    int s = s0;
    for (; s + 4 <= s1; s += 4) {
        int c0 = __ldcs(&g_csr_col[s]),     c1 = __ldcs(&g_csr_col[s + 1]);
        int c2 = __ldcs(&g_csr_col[s + 2]), c3 = __ldcs(&g_csr_col[s + 3]);
        float2 v0 = __ldcs(&g_csr_vals2[s]),     v1 = __ldcs(&g_csr_vals2[s + 1]);
        float2 v2 = __ldcs(&g_csr_vals2[s + 2]), v3 = __ldcs(&g_csr_vals2[s + 3]);
        float2 x0 = __ldg(&X[c0 * 32 + lane]);
        float2 x1 = __ldg(&X[c1 * 32 + lane]);
        float2 x2 = __ldg(&X[c2 * 32 + lane]);
        float2 x3 = __ldg(&X[c3 * 32 + lane]);
        fma2v(aa, v0.x, x0); fma2v(ab, v0.y, x0);
        fma2v(aa, v1.x, x1); fma2v(ab, v1.y, x1);
        fma2v(aa, v2.x, x2); fma2v(ab, v2.y, x2);
        fma2v(aa, v3.x, x3); fma2v(ab, v3.y, x3);
    }
    for (; s < s1; s++) {
        int c = __ldcs(&g_csr_col[s]);
        float2 v = __ldcs(&g_csr_vals2[s]);
        float2 x = __ldg(&X[c * 32 + lane]);
        fma2v(aa, v.x, x); fma2v(ab, v.y, x);
    }
    float2* L1 = (float2*)g_l1;
    __stcs(&L1[warp * 64 + lane], aa);
    __stcs(&L1[warp * 64 + 32 + lane], ab);
}

// ------------------------------------------------------------------
// 6) SPMM layer 2: interleaved l1 -> interleaved l2
// ------------------------------------------------------------------
__global__ void k_spmm_l2() {
    int warp = (blockIdx.x * blockDim.x + threadIdx.x) >> 5;
    int lane = threadIdx.x & 31;
    if (warp >= NTOT) return;
    int s0 = __ldg(&g_rowptr[warp]);
    int s1 = __ldg(&g_rowptr[warp + 1]);
    const float2* X = (const float2*)g_l1;
    float2 aa = make_float2(0.f, 0.f), ab = make_float2(0.f, 0.f);
    int s = s0;
    for (; s + 2 <= s1; s += 2) {
        int c0 = __ldcs(&g_csr_col[s]), c1 = __ldcs(&g_csr_col[s + 1]);
        float2 v0 = __ldcs(&g_csr_vals2[s]), v1 = __ldcs(&g_csr_vals2[s + 1]);
        float2 xa0 = __ldg(&X[c0 * 64 + lane]);
        float2 xb0 = __ldg(&X[c0 * 64 + 32 + lane]);
        float2 xa1 = __ldg(&X[c1 * 64 + lane]);
        float2 xb1 = __ldg(&X[c1 * 64 + 32 + lane]);
        fma2v(aa, v0.x, xa0); fma2v(ab, v0.y, xb0);
        fma2v(aa, v1.x, xa1); fma2v(ab, v1.y, xb1);
    }
    for (; s < s1; s++) {
        int c = __ldcs(&g_csr_col[s]);
        float2 v = __ldcs(&g_csr_vals2[s]);
        float2 xa = __ldg(&X[c * 64 + lane]);
        float2 xb = __ldg(&X[c * 64 + 32 + lane]);
        fma2v(aa, v.x, xa); fma2v(ab, v.y, xb);
    }
    float2* L2 = (float2*)g_l2;
    __stcs(&L2[warp * 64 + lane], aa);
    __stcs(&L2[warp * 64 + 32 + lane], ab);
}

// ------------------------------------------------------------------
// 7) SPMM layer 3 fused with mean: out = (ego + l1 + l2 + l3) / 4
// ------------------------------------------------------------------
__global__ void k_spmm_l3(float* __restrict__ out) {
    int warp = (blockIdx.x * blockDim.x + threadIdx.x) >> 5;
    int lane = threadIdx.x & 31;
    if (warp >= NTOT) return;
    int s0 = __ldg(&g_rowptr[warp]);
    int s1 = __ldg(&g_rowptr[warp + 1]);
    const float2* X = (const float2*)g_l2;
    float2 aa = make_float2(0.f, 0.f), ab = make_float2(0.f, 0.f);
    int s = s0;
    for (; s + 2 <= s1; s += 2) {
        int c0 = __ldcs(&g_csr_col[s]), c1 = __ldcs(&g_csr_col[s + 1]);
        float2 v0 = __ldcs(&g_csr_vals2[s]), v1 = __ldcs(&g_csr_vals2[s + 1]);
        float2 xa0 = __ldg(&X[c0 * 64 + lane]);
        float2 xb0 = __ldg(&X[c0 * 64 + 32 + lane]);
        float2 xa1 = __ldg(&X[c1 * 64 + lane]);
        float2 xb1 = __ldg(&X[c1 * 64 + 32 + lane]);
        fma2v(aa, v0.x, xa0); fma2v(ab, v0.y, xb0);
        fma2v(aa, v1.x, xa1); fma2v(ab, v1.y, xb1);
    }
    for (; s < s1; s++) {
        int c = __ldcs(&g_csr_col[s]);
        float2 v = __ldcs(&g_csr_vals2[s]);
        float2 xa = __ldg(&X[c * 64 + lane]);
        float2 xb = __ldg(&X[c * 64 + 32 + lane]);
        fma2v(aa, v.x, xa); fma2v(ab, v.y, xb);
    }
    const float2* E  = (const float2*)g_ego;
    const float2* L1 = (const float2*)g_l1;
    const float2* L2 = (const float2*)g_l2;
    float2 e  = E[warp * 32 + lane];
    float2 p1 = L1[warp * 64 + lane];
    float2 q1 = L1[warp * 64 + 32 + lane];
    float2 p2 = L2[warp * 64 + lane];
    float2 q2 = L2[warp * 64 + 32 + lane];
    float2* outA = (float2*)out;
    float2* outB = (float2*)out + NTOT * 32;
    __stcs(&outA[warp * 32 + lane],
           make_float2((e.x + p1.x + p2.x + aa.x) * 0.25f,
                       (e.y + p1.y + p2.y + aa.y) * 0.25f));
    __stcs(&outB[warp * 32 + lane],
           make_float2((e.x + q1.x + q2.x + ab.x) * 0.25f,
                       (e.y + q1.y + q2.y + ab.y) * 0.25f));
}

// ------------------------------------------------------------------
// 8) gate mean
// ------------------------------------------------------------------
__global__ void k_final(float* __restrict__ out) {
    out[2 * NTOT * DD] = (float)(g_gate_sum / (double)SS);
}

extern "C" void kernel_launch(void* const* d_in, const int* in_sizes, int n_in,
                              void* d_out, int out_size) {
    const float* user = (const float*)d_in[0];
    const float* item = (const float*)d_in[1];
    const int*   rows = (const int*)d_in[2];
    const int*   cols = (const int*)d_in[3];
    const float* vals = (const float*)d_in[4];
    const int*   sidx = (const int*)d_in[5];
    const float* eps  = (const float*)d_in[6];
    const float* W1   = (const float*)d_in[7];
    const float* b1   = (const float*)d_in[8];
    const float* W2   = (const float*)d_in[9];
    const float* b2   = (const float*)d_in[10];
    float* out = (float*)d_out;

    static int smem_set = 0;
    if (!smem_set) {
        cudaFuncSetAttribute(k_gate_mma,
                             cudaFuncAttributeMaxDynamicSharedMemorySize, GATE_DYN);
        smem_set = 1;
    }

    const int TB = 256;
    k_init_edges<<<(EE + TB - 1) / TB, TB>>>(vals, W1);
    k_prep<<<(NTOT * DD + TB - 1) / TB, TB>>>(user, item, rows, sidx);
    k_scan1<<<SCAN_B, 256>>>();
    k_gate_mma<<<SS / TE, 256, GATE_DYN>>>(rows, cols, vals, sidx, eps, b1, W2, b2);
    k_scan2<<<1, 1024>>>();
    k_scan3<<<SCAN_B, 256>>>();
    k_fill<<<(EE + TB - 1) / TB, TB>>>(rows, cols, vals);

    const int SPMM_BLOCKS = (NTOT * 32 + TB - 1) / TB;
    k_spmm_l1<<<SPMM_BLOCKS, TB>>>();
    k_spmm_l2<<<SPMM_BLOCKS, TB>>>();
    k_spmm_l3<<<SPMM_BLOCKS, TB>>>(out);

    k_final<<<1, 1>>>(out);
}

// round 10
// speedup vs baseline: 1.2765x; 1.0746x over previous
#include <cuda_runtime.h>
#include <cuda_fp16.h>
#include <math.h>
#include <cstdint>

#define NU 100000
#define NTOT 150000
#define DD 64
#define EE 1250000
#define SS 400000
#define TAU 0.2f
#define EDGE_BIAS 0.5f
#define SCAN_B 586   // ceil(NTOT/256)

typedef unsigned long long ull;

// ---- static scratch (no allocations allowed) ----
__device__ float    g_ego[NTOT * DD];
__device__ uint32_t g_ego_h[NTOT * 32];    // ego packed fp16x2 (19.2 MB)
__device__ float    g_l1[NTOT * 2 * DD];   // interleaved: [row][0:64)=orig, [64:128)=masked
__device__ float    g_l2[NTOT * 2 * DD];
__device__ float    g_masked[EE];
__device__ int      g_csr_col[EE];
__device__ float2   g_csr_vals2[EE];       // {val, masked_val}
__device__ int      g_counts[NTOT];
__device__ int      g_fillpos[NTOT];
__device__ int      g_rowptr[NTOT + 1];
__device__ int      g_bsum[1024];
__device__ int      g_lastS[EE];
__device__ uint32_t g_w1h[64 * 64];        // W1 packed fp16x2
__device__ double   g_gate_sum;

// ================= helpers =================
__device__ __forceinline__ uint32_t smem_u32(const void* p) {
    uint32_t a;
    asm("{ .reg .u64 t; cvta.to.shared.u64 t, %1; cvt.u32.u64 %0, t; }" : "=r"(a) : "l"(p));
    return a;
}
__device__ __forceinline__ uint32_t pack_f16x2(float lo, float hi) {
    uint32_t r;
    asm("cvt.rn.f16x2.f32 %0, %1, %2;" : "=r"(r) : "f"(hi), "f"(lo));
    return r;
}
__device__ __forceinline__ void ldsm_x4(uint32_t (&r)[4], uint32_t addr) {
    asm volatile("ldmatrix.sync.aligned.m8n8.x4.shared.b16 {%0,%1,%2,%3}, [%4];"
        : "=r"(r[0]), "=r"(r[1]), "=r"(r[2]), "=r"(r[3]) : "r"(addr));
}
__device__ __forceinline__ void ldsm_x4t(uint32_t (&r)[4], uint32_t addr) {
    asm volatile("ldmatrix.sync.aligned.m8n8.x4.trans.shared.b16 {%0,%1,%2,%3}, [%4];"
        : "=r"(r[0]), "=r"(r[1]), "=r"(r[2]), "=r"(r[3]) : "r"(addr));
}
__device__ __forceinline__ void mma_f16(float (&c)[4], const uint32_t (&a)[4],
                                        uint32_t b0, uint32_t b1) {
    asm volatile(
        "mma.sync.aligned.m16n8k16.row.col.f32.f16.f16.f32 "
        "{%0,%1,%2,%3}, {%4,%5,%6,%7}, {%8,%9}, {%0,%1,%2,%3};"
        : "+f"(c[0]), "+f"(c[1]), "+f"(c[2]), "+f"(c[3])
        : "r"(a[0]), "r"(a[1]), "r"(a[2]), "r"(a[3]), "r"(b0), "r"(b1));
}

// ------------------------------------------------------------------
// 1) per-edge init + pack W1 to fp16
// ------------------------------------------------------------------
__global__ void k_init_edges(const float* __restrict__ vals,
                             const float* __restrict__ W1) {
    int i = blockIdx.x * blockDim.x + threadIdx.x;
    if (i < EE) { g_masked[i] = vals[i]; g_lastS[i] = 0; }
    if (i < NTOT) { g_counts[i] = 0; g_fillpos[i] = 0; }
    if (i < 4096) {
        float v0 = W1[2 * i];
        float v1 = W1[2 * i + 1];
        g_w1h[i] = pack_f16x2(v0, v1);
    }
    if (i == 0) g_gate_sum = 0.0;
}

// ------------------------------------------------------------------
// 2) combined: ego copy (fp32 + packed fp16) + degree count + lastS
// ------------------------------------------------------------------
__global__ void k_prep(const float* __restrict__ user,
                       const float* __restrict__ item,
                       const int* __restrict__ rows,
                       const int* __restrict__ sidx) {
    int i = blockIdx.x * blockDim.x + threadIdx.x;
    if (i < NTOT * 32) {
        int j = 2 * i;
        float v0 = (j < NU * DD) ? user[j] : item[j - NU * DD];
        float v1 = (j + 1 < NU * DD) ? user[j + 1] : item[j + 1 - NU * DD];
        g_ego[j] = v0;
        g_ego[j + 1] = v1;
        g_ego_h[i] = pack_f16x2(v0, v1);
    }
    if (i < EE) atomicAdd(&g_counts[rows[i]], 1);
    if (i < SS) atomicMax(&g_lastS[sidx[i]], i);
}

// ------------------------------------------------------------------
// 3) gate MLP via fp16 mma.sync, single pass, fp16 A staging.
// ------------------------------------------------------------------
#define TE 128
#define A_STRIDE 136
#define B_STRIDE 72
#define A_TILE_B (128 * A_STRIDE * 2)          // 34816
#define B_TILE_B (128 * B_STRIDE * 2)          // 18432
#define GATE_DYN (A_TILE_B + B_TILE_B)         // 53248

__global__ void __launch_bounds__(256)
k_gate_mma(const int* __restrict__ rows, const int* __restrict__ cols,
           const float* __restrict__ vals, const int* __restrict__ sidx,
           const float* __restrict__ eps,
           const float* __restrict__ b1,
           const float* __restrict__ W2, const float* __restrict__ b2) {
    extern __shared__ char dsm[];
    const uint32_t A0 = smem_u32(dsm);
    const uint32_t B0 = A0 + A_TILE_B;

    __shared__ float  b1s[64], W2s[64];
    __shared__ int    eidx[TE];
    __shared__ double gpart[8];

    const int tid  = threadIdx.x;
    const int wid  = tid >> 5;
    const int lane = tid & 31;
    const int base = blockIdx.x * TE;

    if (tid < 64) { b1s[tid] = b1[tid]; W2s[tid] = W2[tid]; }

    // ---- stage B: packed fp16 W1, 16B copies ----
    {
        const uint4* src = (const uint4*)g_w1h;
        for (int i = tid; i < 1024; i += 256) {
            int k = i >> 3, c4 = (i & 7) * 4;
            uint4 v = __ldg(&src[i]);
            *(uint4*)(dsm + A_TILE_B + (uint32_t)(k * B_STRIDE + 2 * c4) * 2u) = v;
        }
    }

    // ---- stage A from packed fp16 ego: pure 16B copies, 2 threads/edge ----
    {
        int e = tid >> 1, p = tid & 1;
        int s = base + e;
        int idx = __ldg(&sidx[s]);
        if (p == 0) eidx[e] = idx;
        int node = p ? __ldg(&cols[idx]) : __ldg(&rows[idx]);
        const uint4* src = (const uint4*)(g_ego_h + node * 32);  // 8 uint4 = 64 halfs
        uint32_t rowoff = (uint32_t)(e * A_STRIDE + p * DD) * 2u;
#pragma unroll
        for (int j = 0; j < 8; j++) {
            uint4 v = __ldg(&src[j]);
            *(uint4*)(dsm + rowoff + (uint32_t)j * 16u) = v;
        }
    }
    __syncthreads();

    // ---- mainloop: 8 k-steps, 4 n16-blocks ----
    float C[8][4];
#pragma unroll
    for (int n = 0; n < 8; n++)
#pragma unroll
        for (int q = 0; q < 4; q++) C[n][q] = 0.f;

    const uint32_t a_lane_off =
        (uint32_t)((wid * 16 + (lane & 15)) * A_STRIDE + (lane >> 4) * 8) * 2u;
    const int bg  = lane >> 3;
    const int br  = lane & 7;
    const int b_krow_off = (bg & 1) * 8 + br;
    const int b_ncol_off = (bg >> 1) * 8;

#pragma unroll
    for (int k = 0; k < 8; k++) {
        uint32_t a[4];
        ldsm_x4(a, A0 + a_lane_off + (uint32_t)(k * 16 * 2));
        uint32_t b_base = B0 +
            (uint32_t)((k * 16 + b_krow_off) * B_STRIDE + b_ncol_off) * 2u;
#pragma unroll
        for (int nb = 0; nb < 4; nb++) {
            uint32_t b[4];
            ldsm_x4t(b, b_base + (uint32_t)(nb * 16 * 2));
            mma_f16(C[2 * nb],     a, b[0], b[1]);
            mma_f16(C[2 * nb + 1], a, b[2], b[3]);
        }
    }

    // ---- epilogue ----
    const int qr = lane >> 2;
    const int qc = (lane & 3) * 2;
    float pl = 0.f, ph = 0.f;
#pragma unroll
    for (int n = 0; n < 8; n++) {
        int c0 = n * 8 + qc, c1 = c0 + 1;
        pl += fmaxf(C[n][0] + b1s[c0], 0.f) * W2s[c0]
            + fmaxf(C[n][1] + b1s[c1], 0.f) * W2s[c1];
        ph += fmaxf(C[n][2] + b1s[c0], 0.f) * W2s[c0]
            + fmaxf(C[n][3] + b1s[c1], 0.f) * W2s[c1];
    }
    pl += __shfl_xor_sync(0xffffffffu, pl, 1);
    pl += __shfl_xor_sync(0xffffffffu, pl, 2);
    ph += __shfl_xor_sync(0xffffffffu, ph, 1);
    ph += __shfl_xor_sync(0xffffffffu, ph, 2);

    double gsum = 0.0;
    if ((lane & 3) == 0) {
        float b2v = __ldg(b2);
        float logit[2] = {pl + b2v, ph + b2v};
#pragma unroll
        for (int h = 0; h < 2; h++) {
            int e = wid * 16 + qr + h * 8;
            int s = base + e;
            float ee = __ldg(&eps[s]) * (1.f - 2e-6f) + 1e-6f;
            float gumbel = logf(ee) - log1pf(-ee);
            float gate = 1.f / (1.f + expf(-(logit[h] + gumbel) / TAU)) + EDGE_BIAS;
            gsum += (double)gate;
            int idx = eidx[e];
            if (g_lastS[idx] == s) g_masked[idx] = vals[idx] * gate;
        }
    }
#pragma unroll
    for (int off = 16; off; off >>= 1)
        gsum += __shfl_xor_sync(0xffffffffu, gsum, off);
    if (lane == 0) gpart[wid] = gsum;
    __syncthreads();
    if (tid == 0) {
        double t = 0.0;
#pragma unroll
        for (int i = 0; i < 8; i++) t += gpart[i];
        atomicAdd(&g_gate_sum, t);
    }
}

// ------------------------------------------------------------------
// 4) CSR scan (3-phase) + fill
// ------------------------------------------------------------------
__global__ void k_scan1() {
    __shared__ int sh[256];
    int i = blockIdx.x * 256 + threadIdx.x;
    int v = (i < NTOT) ? g_counts[i] : 0;
    sh[threadIdx.x] = v;
    __syncthreads();
    for (int off = 128; off; off >>= 1) {
        if (threadIdx.x < off) sh[threadIdx.x] += sh[threadIdx.x + off];
        __syncthreads();
    }
    if (threadIdx.x == 0) g_bsum[blockIdx.x] = sh[0];
}

__global__ void k_scan2() {
    __shared__ int sh[1024];
    int t = threadIdx.x;
    int v = (t < SCAN_B) ? g_bsum[t] : 0;
    sh[t] = v;
    __syncthreads();
    for (int off = 1; off < 1024; off <<= 1) {
        int u = (t >= off) ? sh[t - off] : 0;
        __syncthreads();
        sh[t] += u;
        __syncthreads();
    }
    if (t < SCAN_B) g_bsum[t] = sh[t] - v;  // exclusive
}

__global__ void k_scan3() {
    __shared__ int sh[256];
    int i = blockIdx.x * 256 + threadIdx.x;
    int v = (i < NTOT) ? g_counts[i] : 0;
    sh[threadIdx.x] = v;
    __syncthreads();
    for (int off = 1; off < 256; off <<= 1) {
        int u = (threadIdx.x >= off) ? sh[threadIdx.x - off] : 0;
        __syncthreads();
        sh[threadIdx.x] += u;
        __syncthreads();
    }
    if (i < NTOT) g_rowptr[i] = g_bsum[blockIdx.x] + sh[threadIdx.x] - v;
    if (i == 0) g_rowptr[NTOT] = EE;
}

__global__ void k_fill(const int* __restrict__ rows, const int* __restrict__ cols,
                       const float* __restrict__ vals) {
    int e = blockIdx.x * blockDim.x + threadIdx.x;
    if (e >= EE) return;
    int r = rows[e];
    int slot = g_rowptr[r] + atomicAdd(&g_fillpos[r], 1);
    g_csr_col[slot] = cols[e];
    g_csr_vals2[slot] = make_float2(vals[e], g_masked[e]);
}

// ------------------------------------------------------------------
// 5) SPMM layer 1: both chains gather ego once -> interleaved l1
// ------------------------------------------------------------------
__device__ __forceinline__ void fma2v(float2& a, float v, float2 x) {
    a.x = fmaf(v, x.x, a.x); a.y = fmaf(v, x.y, a.y);
}

__global__ void k_spmm_l1() {
    int warp = (blockIdx.x * blockDim.x + threadIdx.x) >> 5;
    int lane = threadIdx.x & 31;
    if (warp >= NTOT) return;
    int s0 = __ldg(&g_rowptr[warp]);
    int s1 = __ldg(&g_rowptr[warp + 1]);
    const float2* X = (const float2*)g_ego;
    float2 aa = make_float2(0.f, 0.f), ab = make_float2(0.f, 0.f);
    int s = s0;
    for (; s + 4 <= s1; s += 4) {
        int c0 = __ldcs(&g_csr_col[s]),     c1 = __ldcs(&g_csr_col[s + 1]);
        int c2 = __ldcs(&g_csr_col[s + 2]), c3 = __ldcs(&g_csr_col[s + 3]);
        float2 v0 = __ldcs(&g_csr_vals2[s]),     v1 = __ldcs(&g_csr_vals2[s + 1]);
        float2 v2 = __ldcs(&g_csr_vals2[s + 2]), v3 = __ldcs(&g_csr_vals2[s + 3]);
        float2 x0 = __ldg(&X[c0 * 32 + lane]);
        float2 x1 = __ldg(&X[c1 * 32 + lane]);
        float2 x2 = __ldg(&X[c2 * 32 + lane]);
        float2 x3 = __ldg(&X[c3 * 32 + lane]);
        fma2v(aa, v0.x, x0); fma2v(ab, v0.y, x0);
        fma2v(aa, v1.x, x1); fma2v(ab, v1.y, x1);
        fma2v(aa, v2.x, x2); fma2v(ab, v2.y, x2);
        fma2v(aa, v3.x, x3); fma2v(ab, v3.y, x3);
    }
    for (; s < s1; s++) {
        int c = __ldcs(&g_csr_col[s]);
        float2 v = __ldcs(&g_csr_vals2[s]);
        float2 x = __ldg(&X[c * 32 + lane]);
        fma2v(aa, v.x, x); fma2v(ab, v.y, x);
    }
    float2* L1 = (float2*)g_l1;
    __stcs(&L1[warp * 64 + lane], aa);
    __stcs(&L1[warp * 64 + 32 + lane], ab);
}

// ------------------------------------------------------------------
// 6) SPMM layer 2: interleaved l1 -> interleaved l2, unroll 4
// ------------------------------------------------------------------
__global__ void k_spmm_l2() {
    int warp = (blockIdx.x * blockDim.x + threadIdx.x) >> 5;
    int lane = threadIdx.x & 31;
    if (warp >= NTOT) return;
    int s0 = __ldg(&g_rowptr[warp]);
    int s1 = __ldg(&g_rowptr[warp + 1]);
    const float2* X = (const float2*)g_l1;
    float2 aa = make_float2(0.f, 0.f), ab = make_float2(0.f, 0.f);
    int s = s0;
    for (; s + 4 <= s1; s += 4) {
        int c0 = __ldcs(&g_csr_col[s]),     c1 = __ldcs(&g_csr_col[s + 1]);
        int c2 = __ldcs(&g_csr_col[s + 2]), c3 = __ldcs(&g_csr_col[s + 3]);
        float2 v0 = __ldcs(&g_csr_vals2[s]),     v1 = __ldcs(&g_csr_vals2[s + 1]);
        float2 v2 = __ldcs(&g_csr_vals2[s + 2]), v3 = __ldcs(&g_csr_vals2[s + 3]);
        float2 xa0 = __ldg(&X[c0 * 64 + lane]);
        float2 xb0 = __ldg(&X[c0 * 64 + 32 + lane]);
        float2 xa1 = __ldg(&X[c1 * 64 + lane]);
        float2 xb1 = __ldg(&X[c1 * 64 + 32 + lane]);
        float2 xa2 = __ldg(&X[c2 * 64 + lane]);
        float2 xb2 = __ldg(&X[c2 * 64 + 32 + lane]);
        float2 xa3 = __ldg(&X[c3 * 64 + lane]);
        float2 xb3 = __ldg(&X[c3 * 64 + 32 + lane]);
        fma2v(aa, v0.x, xa0); fma2v(ab, v0.y, xb0);
        fma2v(aa, v1.x, xa1); fma2v(ab, v1.y, xb1);
        fma2v(aa, v2.x, xa2); fma2v(ab, v2.y, xb2);
        fma2v(aa, v3.x, xa3); fma2v(ab, v3.y, xb3);
    }
    for (; s < s1; s++) {
        int c = __ldcs(&g_csr_col[s]);
        float2 v = __ldcs(&g_csr_vals2[s]);
        float2 xa = __ldg(&X[c * 64 + lane]);
        float2 xb = __ldg(&X[c * 64 + 32 + lane]);
        fma2v(aa, v.x, xa); fma2v(ab, v.y, xb);
    }
    float2* L2 = (float2*)g_l2;
    __stcs(&L2[warp * 64 + lane], aa);
    __stcs(&L2[warp * 64 + 32 + lane], ab);
}

// ------------------------------------------------------------------
// 7) SPMM layer 3 fused with mean, unroll 4
// ------------------------------------------------------------------
__global__ void k_spmm_l3(float* __restrict__ out) {
    int warp = (blockIdx.x * blockDim.x + threadIdx.x) >> 5;
    int lane = threadIdx.x & 31;
    if (warp >= NTOT) return;
    int s0 = __ldg(&g_rowptr[warp]);
    int s1 = __ldg(&g_rowptr[warp + 1]);
    const float2* X = (const float2*)g_l2;
    float2 aa = make_float2(0.f, 0.f), ab = make_float2(0.f, 0.f);
    int s = s0;
    for (; s + 4 <= s1; s += 4) {
        int c0 = __ldcs(&g_csr_col[s]),     c1 = __ldcs(&g_csr_col[s + 1]);
        int c2 = __ldcs(&g_csr_col[s + 2]), c3 = __ldcs(&g_csr_col[s + 3]);
        float2 v0 = __ldcs(&g_csr_vals2[s]),     v1 = __ldcs(&g_csr_vals2[s + 1]);
        float2 v2 = __ldcs(&g_csr_vals2[s + 2]), v3 = __ldcs(&g_csr_vals2[s + 3]);
        float2 xa0 = __ldg(&X[c0 * 64 + lane]);
        float2 xb0 = __ldg(&X[c0 * 64 + 32 + lane]);
        float2 xa1 = __ldg(&X[c1 * 64 + lane]);
        float2 xb1 = __ldg(&X[c1 * 64 + 32 + lane]);
        float2 xa2 = __ldg(&X[c2 * 64 + lane]);
        float2 xb2 = __ldg(&X[c2 * 64 + 32 + lane]);
        float2 xa3 = __ldg(&X[c3 * 64 + lane]);
        float2 xb3 = __ldg(&X[c3 * 64 + 32 + lane]);
        fma2v(aa, v0.x, xa0); fma2v(ab, v0.y, xb0);
        fma2v(aa, v1.x, xa1); fma2v(ab, v1.y, xb1);
        fma2v(aa, v2.x, xa2); fma2v(ab, v2.y, xb2);
        fma2v(aa, v3.x, xa3); fma2v(ab, v3.y, xb3);
    }
    for (; s < s1; s++) {
        int c = __ldcs(&g_csr_col[s]);
        float2 v = __ldcs(&g_csr_vals2[s]);
        float2 xa = __ldg(&X[c * 64 + lane]);
        float2 xb = __ldg(&X[c * 64 + 32 + lane]);
        fma2v(aa, v.x, xa); fma2v(ab, v.y, xb);
    }
    const float2* E  = (const float2*)g_ego;
    const float2* L1 = (const float2*)g_l1;
    const float2* L2 = (const float2*)g_l2;
    float2 e  = E[warp * 32 + lane];
    float2 p1 = L1[warp * 64 + lane];
    float2 q1 = L1[warp * 64 + 32 + lane];
    float2 p2 = L2[warp * 64 + lane];
    float2 q2 = L2[warp * 64 + 32 + lane];
    float2* outA = (float2*)out;
    float2* outB = (float2*)out + NTOT * 32;
    __stcs(&outA[warp * 32 + lane],
           make_float2((e.x + p1.x + p2.x + aa.x) * 0.25f,
                       (e.y + p1.y + p2.y + aa.y) * 0.25f));
    __stcs(&outB[warp * 32 + lane],
           make_float2((e.x + q1.x + q2.x + ab.x) * 0.25f,
                       (e.y + q1.y + q2.y + ab.y) * 0.25f));
}

// ------------------------------------------------------------------
// 8) gate mean
// ------------------------------------------------------------------
__global__ void k_final(float* __restrict__ out) {
    out[2 * NTOT * DD] = (float)(g_gate_sum / (double)SS);
}

extern "C" void kernel_launch(void* const* d_in, const int* in_sizes, int n_in,
                              void* d_out, int out_size) {
    const float* user = (const float*)d_in[0];
    const float* item = (const float*)d_in[1];
    const int*   rows = (const int*)d_in[2];
    const int*   cols = (const int*)d_in[3];
    const float* vals = (const float*)d_in[4];
    const int*   sidx = (const int*)d_in[5];
    const float* eps  = (const float*)d_in[6];
    const float* W1   = (const float*)d_in[7];
    const float* b1   = (const float*)d_in[8];
    const float* W2   = (const float*)d_in[9];
    const float* b2   = (const float*)d_in[10];
    float* out = (float*)d_out;

    static int smem_set = 0;
    if (!smem_set) {
        cudaFuncSetAttribute(k_gate_mma,
                             cudaFuncAttributeMaxDynamicSharedMemorySize, GATE_DYN);
        smem_set = 1;
    }

    const int TB = 256;
    k_init_edges<<<(EE + TB - 1) / TB, TB>>>(vals, W1);
    k_prep<<<(NTOT * DD + TB - 1) / TB, TB>>>(user, item, rows, sidx);
    k_scan1<<<SCAN_B, 256>>>();
    k_gate_mma<<<SS / TE, 256, GATE_DYN>>>(rows, cols, vals, sidx, eps, b1, W2, b2);
    k_scan2<<<1, 1024>>>();
    k_scan3<<<SCAN_B, 256>>>();
    k_fill<<<(EE + TB - 1) / TB, TB>>>(rows, cols, vals);

    const int SPMM_BLOCKS = (NTOT * 32 + TB - 1) / TB;
    k_spmm_l1<<<SPMM_BLOCKS, TB>>>();
    k_spmm_l2<<<SPMM_BLOCKS, TB>>>();
    k_spmm_l3<<<SPMM_BLOCKS, TB>>>(out);

    k_final<<<1, 1>>>(out);
}

// round 11
// speedup vs baseline: 1.3610x; 1.0662x over previous
#include <cuda_runtime.h>
#include <cuda_fp16.h>
#include <math.h>
#include <cstdint>

#define NU 100000
#define NTOT 150000
#define DD 64
#define EE 1250000
#define SS 400000
#define TAU 0.2f
#define EDGE_BIAS 0.5f
#define SCAN_B 586   // ceil(NTOT/256)

typedef unsigned long long ull;

// ---- static scratch (no allocations allowed) ----
__device__ float    g_ego[NTOT * DD];
__device__ uint32_t g_ego_h[NTOT * 32];    // ego packed fp16x2 (19.2 MB)
__device__ float    g_l1[NTOT * 2 * DD];   // interleaved fp32
__device__ float    g_l2[NTOT * 2 * DD];
__device__ uint32_t g_l1h[NTOT * 64];      // interleaved fp16x2 mirror (38.4 MB)
__device__ uint32_t g_l2h[NTOT * 64];
__device__ float    g_masked[EE];
__device__ int      g_csr_col[EE];
__device__ float2   g_csr_vals2[EE];       // {val, masked_val}
__device__ int      g_counts[NTOT];
__device__ int      g_fillpos[NTOT];
__device__ int      g_rowptr[NTOT + 1];
__device__ int      g_bsum[1024];
__device__ int      g_lastS[EE];
__device__ uint32_t g_w1h[64 * 64];        // W1 packed fp16x2
__device__ double   g_gate_sum;

// ================= helpers =================
__device__ __forceinline__ uint32_t smem_u32(const void* p) {
    uint32_t a;
    asm("{ .reg .u64 t; cvta.to.shared.u64 t, %1; cvt.u32.u64 %0, t; }" : "=r"(a) : "l"(p));
    return a;
}
__device__ __forceinline__ uint32_t pack_f16x2(float lo, float hi) {
    uint32_t r;
    asm("cvt.rn.f16x2.f32 %0, %1, %2;" : "=r"(r) : "f"(hi), "f"(lo));
    return r;
}
__device__ __forceinline__ float2 unpack_f16x2(uint32_t u) {
    __half2 h = *reinterpret_cast<__half2*>(&u);
    return __half22float2(h);
}
__device__ __forceinline__ void ldsm_x4(uint32_t (&r)[4], uint32_t addr) {
    asm volatile("ldmatrix.sync.aligned.m8n8.x4.shared.b16 {%0,%1,%2,%3}, [%4];"
        : "=r"(r[0]), "=r"(r[1]), "=r"(r[2]), "=r"(r[3]) : "r"(addr));
}
__device__ __forceinline__ void ldsm_x4t(uint32_t (&r)[4], uint32_t addr) {
    asm volatile("ldmatrix.sync.aligned.m8n8.x4.trans.shared.b16 {%0,%1,%2,%3}, [%4];"
        : "=r"(r[0]), "=r"(r[1]), "=r"(r[2]), "=r"(r[3]) : "r"(addr));
}
__device__ __forceinline__ void mma_f16(float (&c)[4], const uint32_t (&a)[4],
                                        uint32_t b0, uint32_t b1) {
    asm volatile(
        "mma.sync.aligned.m16n8k16.row.col.f32.f16.f16.f32 "
        "{%0,%1,%2,%3}, {%4,%5,%6,%7}, {%8,%9}, {%0,%1,%2,%3};"
        : "+f"(c[0]), "+f"(c[1]), "+f"(c[2]), "+f"(c[3])
        : "r"(a[0]), "r"(a[1]), "r"(a[2]), "r"(a[3]), "r"(b0), "r"(b1));
}
__device__ __forceinline__ void fma2v(float2& a, float v, float2 x) {
    a.x = fmaf(v, x.x, a.x); a.y = fmaf(v, x.y, a.y);
}

// ------------------------------------------------------------------
// 1) per-edge init + pack W1 to fp16
// ------------------------------------------------------------------
__global__ void k_init_edges(const float* __restrict__ vals,
                             const float* __restrict__ W1) {
    int i = blockIdx.x * blockDim.x + threadIdx.x;
    if (i < EE) { g_masked[i] = vals[i]; g_lastS[i] = 0; }
    if (i < NTOT) { g_counts[i] = 0; g_fillpos[i] = 0; }
    if (i < 4096) {
        float v0 = W1[2 * i];
        float v1 = W1[2 * i + 1];
        g_w1h[i] = pack_f16x2(v0, v1);
    }
    if (i == 0) g_gate_sum = 0.0;
}

// ------------------------------------------------------------------
// 2) combined: ego copy (fp32 + packed fp16) + degree count + lastS
// ------------------------------------------------------------------
__global__ void k_prep(const float* __restrict__ user,
                       const float* __restrict__ item,
                       const int* __restrict__ rows,
                       const int* __restrict__ sidx) {
    int i = blockIdx.x * blockDim.x + threadIdx.x;
    if (i < NTOT * 32) {
        int j = 2 * i;
        float v0 = (j < NU * DD) ? user[j] : item[j - NU * DD];
        float v1 = (j + 1 < NU * DD) ? user[j + 1] : item[j + 1 - NU * DD];
        g_ego[j] = v0;
        g_ego[j + 1] = v1;
        g_ego_h[i] = pack_f16x2(v0, v1);
    }
    if (i < EE) atomicAdd(&g_counts[rows[i]], 1);
    if (i < SS) atomicMax(&g_lastS[sidx[i]], i);
}

// ------------------------------------------------------------------
// 3) gate MLP via fp16 mma.sync (R10 proven, 86us)
// ------------------------------------------------------------------
#define TE 128
#define A_STRIDE 136
#define B_STRIDE 72
#define A_TILE_B (128 * A_STRIDE * 2)
#define B_TILE_B (128 * B_STRIDE * 2)
#define GATE_DYN (A_TILE_B + B_TILE_B)

__global__ void __launch_bounds__(256)
k_gate_mma(const int* __restrict__ rows, const int* __restrict__ cols,
           const float* __restrict__ vals, const int* __restrict__ sidx,
           const float* __restrict__ eps,
           const float* __restrict__ b1,
           const float* __restrict__ W2, const float* __restrict__ b2) {
    extern __shared__ char dsm[];
    const uint32_t A0 = smem_u32(dsm);
    const uint32_t B0 = A0 + A_TILE_B;

    __shared__ float  b1s[64], W2s[64];
    __shared__ int    eidx[TE];
    __shared__ double gpart[8];

    const int tid  = threadIdx.x;
    const int wid  = tid >> 5;
    const int lane = tid & 31;
    const int base = blockIdx.x * TE;

    if (tid < 64) { b1s[tid] = b1[tid]; W2s[tid] = W2[tid]; }

    {
        const uint4* src = (const uint4*)g_w1h;
        for (int i = tid; i < 1024; i += 256) {
            int k = i >> 3, c4 = (i & 7) * 4;
            uint4 v = __ldg(&src[i]);
            *(uint4*)(dsm + A_TILE_B + (uint32_t)(k * B_STRIDE + 2 * c4) * 2u) = v;
        }
    }
    {
        int e = tid >> 1, p = tid & 1;
        int s = base + e;
        int idx = __ldg(&sidx[s]);
        if (p == 0) eidx[e] = idx;
        int node = p ? __ldg(&cols[idx]) : __ldg(&rows[idx]);
        const uint4* src = (const uint4*)(g_ego_h + node * 32);
        uint32_t rowoff = (uint32_t)(e * A_STRIDE + p * DD) * 2u;
#pragma unroll
        for (int j = 0; j < 8; j++) {
            uint4 v = __ldg(&src[j]);
            *(uint4*)(dsm + rowoff + (uint32_t)j * 16u) = v;
        }
    }
    __syncthreads();

    float C[8][4];
#pragma unroll
    for (int n = 0; n < 8; n++)
#pragma unroll
        for (int q = 0; q < 4; q++) C[n][q] = 0.f;

    const uint32_t a_lane_off =
        (uint32_t)((wid * 16 + (lane & 15)) * A_STRIDE + (lane >> 4) * 8) * 2u;
    const int bg  = lane >> 3;
    const int br  = lane & 7;
    const int b_krow_off = (bg & 1) * 8 + br;
    const int b_ncol_off = (bg >> 1) * 8;

#pragma unroll
    for (int k = 0; k < 8; k++) {
        uint32_t a[4];
        ldsm_x4(a, A0 + a_lane_off + (uint32_t)(k * 16 * 2));
        uint32_t b_base = B0 +
            (uint32_t)((k * 16 + b_krow_off) * B_STRIDE + b_ncol_off) * 2u;
#pragma unroll
        for (int nb = 0; nb < 4; nb++) {
            uint32_t b[4];
            ldsm_x4t(b, b_base + (uint32_t)(nb * 16 * 2));
            mma_f16(C[2 * nb],     a, b[0], b[1]);
            mma_f16(C[2 * nb + 1], a, b[2], b[3]);
        }
    }

    const int qr = lane >> 2;
    const int qc = (lane & 3) * 2;
    float pl = 0.f, ph = 0.f;
#pragma unroll
    for (int n = 0; n < 8; n++) {
        int c0 = n * 8 + qc, c1 = c0 + 1;
        pl += fmaxf(C[n][0] + b1s[c0], 0.f) * W2s[c0]
            + fmaxf(C[n][1] + b1s[c1], 0.f) * W2s[c1];
        ph += fmaxf(C[n][2] + b1s[c0], 0.f) * W2s[c0]
            + fmaxf(C[n][3] + b1s[c1], 0.f) * W2s[c1];
    }
    pl += __shfl_xor_sync(0xffffffffu, pl, 1);
    pl += __shfl_xor_sync(0xffffffffu, pl, 2);
    ph += __shfl_xor_sync(0xffffffffu, ph, 1);
    ph += __shfl_xor_sync(0xffffffffu, ph, 2);

    double gsum = 0.0;
    if ((lane & 3) == 0) {
        float b2v = __ldg(b2);
        float logit[2] = {pl + b2v, ph + b2v};
#pragma unroll
        for (int h = 0; h < 2; h++) {
            int e = wid * 16 + qr + h * 8;
            int s = base + e;
            float ee = __ldg(&eps[s]) * (1.f - 2e-6f) + 1e-6f;
            float gumbel = logf(ee) - log1pf(-ee);
            float gate = 1.f / (1.f + expf(-(logit[h] + gumbel) / TAU)) + EDGE_BIAS;
            gsum += (double)gate;
            int idx = eidx[e];
            if (g_lastS[idx] == s) g_masked[idx] = vals[idx] * gate;
        }
    }
#pragma unroll
    for (int off = 16; off; off >>= 1)
        gsum += __shfl_xor_sync(0xffffffffu, gsum, off);
    if (lane == 0) gpart[wid] = gsum;
    __syncthreads();
    if (tid == 0) {
        double t = 0.0;
#pragma unroll
        for (int i = 0; i < 8; i++) t += gpart[i];
        atomicAdd(&g_gate_sum, t);
    }
}

// ------------------------------------------------------------------
// 4) CSR scan (3-phase) + fill
// ------------------------------------------------------------------
__global__ void k_scan1() {
    __shared__ int sh[256];
    int i = blockIdx.x * 256 + threadIdx.x;
    int v = (i < NTOT) ? g_counts[i] : 0;
    sh[threadIdx.x] = v;
    __syncthreads();
    for (int off = 128; off; off >>= 1) {
        if (threadIdx.x < off) sh[threadIdx.x] += sh[threadIdx.x + off];
        __syncthreads();
    }
    if (threadIdx.x == 0) g_bsum[blockIdx.x] = sh[0];
}

__global__ void k_scan2() {
    __shared__ int sh[1024];
    int t = threadIdx.x;
    int v = (t < SCAN_B) ? g_bsum[t] : 0;
    sh[t] = v;
    __syncthreads();
    for (int off = 1; off < 1024; off <<= 1) {
        int u = (t >= off) ? sh[t - off] : 0;
        __syncthreads();
        sh[t] += u;
        __syncthreads();
    }
    if (t < SCAN_B) g_bsum[t] = sh[t] - v;  // exclusive
}

__global__ void k_scan3() {
    __shared__ int sh[256];
    int i = blockIdx.x * 256 + threadIdx.x;
    int v = (i < NTOT) ? g_counts[i] : 0;
    sh[threadIdx.x] = v;
    __syncthreads();
    for (int off = 1; off < 256; off <<= 1) {
        int u = (threadIdx.x >= off) ? sh[threadIdx.x - off] : 0;
        __syncthreads();
        sh[threadIdx.x] += u;
        __syncthreads();
    }
    if (i < NTOT) g_rowptr[i] = g_bsum[blockIdx.x] + sh[threadIdx.x] - v;
    if (i == 0) g_rowptr[NTOT] = EE;
}

__global__ void k_fill(const int* __restrict__ rows, const int* __restrict__ cols,
                       const float* __restrict__ vals) {
    int e = blockIdx.x * blockDim.x + threadIdx.x;
    if (e >= EE) return;
    int r = rows[e];
    int slot = g_rowptr[r] + atomicAdd(&g_fillpos[r], 1);
    g_csr_col[slot] = cols[e];
    g_csr_vals2[slot] = make_float2(vals[e], g_masked[e]);
}

// ------------------------------------------------------------------
// 5) SPMM layer 1: gather fp16 ego (4B/lane), write fp32 + fp16 mirror
// ------------------------------------------------------------------
__global__ void k_spmm_l1() {
    int warp = (blockIdx.x * blockDim.x + threadIdx.x) >> 5;
    int lane = threadIdx.x & 31;
    if (warp >= NTOT) return;
    int s0 = __ldg(&g_rowptr[warp]);
    int s1 = __ldg(&g_rowptr[warp + 1]);
    float2 aa = make_float2(0.f, 0.f), ab = make_float2(0.f, 0.f);
    int s = s0;
    for (; s + 4 <= s1; s += 4) {
        int c0 = __ldcs(&g_csr_col[s]),     c1 = __ldcs(&g_csr_col[s + 1]);
        int c2 = __ldcs(&g_csr_col[s + 2]), c3 = __ldcs(&g_csr_col[s + 3]);
        float2 v0 = __ldcs(&g_csr_vals2[s]),     v1 = __ldcs(&g_csr_vals2[s + 1]);
        float2 v2 = __ldcs(&g_csr_vals2[s + 2]), v3 = __ldcs(&g_csr_vals2[s + 3]);
        float2 x0 = unpack_f16x2(__ldg(&g_ego_h[c0 * 32 + lane]));
        float2 x1 = unpack_f16x2(__ldg(&g_ego_h[c1 * 32 + lane]));
        float2 x2 = unpack_f16x2(__ldg(&g_ego_h[c2 * 32 + lane]));
        float2 x3 = unpack_f16x2(__ldg(&g_ego_h[c3 * 32 + lane]));
        fma2v(aa, v0.x, x0); fma2v(ab, v0.y, x0);
        fma2v(aa, v1.x, x1); fma2v(ab, v1.y, x1);
        fma2v(aa, v2.x, x2); fma2v(ab, v2.y, x2);
        fma2v(aa, v3.x, x3); fma2v(ab, v3.y, x3);
    }
    for (; s < s1; s++) {
        int c = __ldcs(&g_csr_col[s]);
        float2 v = __ldcs(&g_csr_vals2[s]);
        float2 x = unpack_f16x2(__ldg(&g_ego_h[c * 32 + lane]));
        fma2v(aa, v.x, x); fma2v(ab, v.y, x);
    }
    float2* L1 = (float2*)g_l1;
    __stcs(&L1[warp * 64 + lane], aa);
    __stcs(&L1[warp * 64 + 32 + lane], ab);
    __stcs(&g_l1h[warp * 64 + lane], pack_f16x2(aa.x, aa.y));
    __stcs(&g_l1h[warp * 64 + 32 + lane], pack_f16x2(ab.x, ab.y));
}

// ------------------------------------------------------------------
// 6) SPMM layer 2: gather fp16 l1 (8B/lane), write fp32 + fp16 mirror
// ------------------------------------------------------------------
__global__ void k_spmm_l2() {
    int warp = (blockIdx.x * blockDim.x + threadIdx.x) >> 5;
    int lane = threadIdx.x & 31;
    if (warp >= NTOT) return;
    int s0 = __ldg(&g_rowptr[warp]);
    int s1 = __ldg(&g_rowptr[warp + 1]);
    float2 aa = make_float2(0.f, 0.f), ab = make_float2(0.f, 0.f);
    int s = s0;
    for (; s + 4 <= s1; s += 4) {
        int c0 = __ldcs(&g_csr_col[s]),     c1 = __ldcs(&g_csr_col[s + 1]);
        int c2 = __ldcs(&g_csr_col[s + 2]), c3 = __ldcs(&g_csr_col[s + 3]);
        float2 v0 = __ldcs(&g_csr_vals2[s]),     v1 = __ldcs(&g_csr_vals2[s + 1]);
        float2 v2 = __ldcs(&g_csr_vals2[s + 2]), v3 = __ldcs(&g_csr_vals2[s + 3]);
        float2 xa0 = unpack_f16x2(__ldg(&g_l1h[c0 * 64 + lane]));
        float2 xb0 = unpack_f16x2(__ldg(&g_l1h[c0 * 64 + 32 + lane]));
        float2 xa1 = unpack_f16x2(__ldg(&g_l1h[c1 * 64 + lane]));
        float2 xb1 = unpack_f16x2(__ldg(&g_l1h[c1 * 64 + 32 + lane]));
        float2 xa2 = unpack_f16x2(__ldg(&g_l1h[c2 * 64 + lane]));
        float2 xb2 = unpack_f16x2(__ldg(&g_l1h[c2 * 64 + 32 + lane]));
        float2 xa3 = unpack_f16x2(__ldg(&g_l1h[c3 * 64 + lane]));
        float2 xb3 = unpack_f16x2(__ldg(&g_l1h[c3 * 64 + 32 + lane]));
        fma2v(aa, v0.x, xa0); fma2v(ab, v0.y, xb0);
        fma2v(aa, v1.x, xa1); fma2v(ab, v1.y, xb1);
        fma2v(aa, v2.x, xa2); fma2v(ab, v2.y, xb2);
        fma2v(aa, v3.x, xa3); fma2v(ab, v3.y, xb3);
    }
    for (; s < s1; s++) {
        int c = __ldcs(&g_csr_col[s]);
        float2 v = __ldcs(&g_csr_vals2[s]);
        float2 xa = unpack_f16x2(__ldg(&g_l1h[c * 64 + lane]));
        float2 xb = unpack_f16x2(__ldg(&g_l1h[c * 64 + 32 + lane]));
        fma2v(aa, v.x, xa); fma2v(ab, v.y, xb);
    }
    float2* L2 = (float2*)g_l2;
    __stcs(&L2[warp * 64 + lane], aa);
    __stcs(&L2[warp * 64 + 32 + lane], ab);
    __stcs(&g_l2h[warp * 64 + lane], pack_f16x2(aa.x, aa.y));
    __stcs(&g_l2h[warp * 64 + 32 + lane], pack_f16x2(ab.x, ab.y));
}

// ------------------------------------------------------------------
// 7) SPMM layer 3: gather fp16 l2, fused mean with fp32 ego/l1/l2
// ------------------------------------------------------------------
__global__ void k_spmm_l3(float* __restrict__ out) {
    int warp = (blockIdx.x * blockDim.x + threadIdx.x) >> 5;
    int lane = threadIdx.x & 31;
    if (warp >= NTOT) return;
    int s0 = __ldg(&g_rowptr[warp]);
    int s1 = __ldg(&g_rowptr[warp + 1]);
    float2 aa = make_float2(0.f, 0.f), ab = make_float2(0.f, 0.f);
    int s = s0;
    for (; s + 4 <= s1; s += 4) {
        int c0 = __ldcs(&g_csr_col[s]),     c1 = __ldcs(&g_csr_col[s + 1]);
        int c2 = __ldcs(&g_csr_col[s + 2]), c3 = __ldcs(&g_csr_col[s + 3]);
        float2 v0 = __ldcs(&g_csr_vals2[s]),     v1 = __ldcs(&g_csr_vals2[s + 1]);
        float2 v2 = __ldcs(&g_csr_vals2[s + 2]), v3 = __ldcs(&g_csr_vals2[s + 3]);
        float2 xa0 = unpack_f16x2(__ldg(&g_l2h[c0 * 64 + lane]));
        float2 xb0 = unpack_f16x2(__ldg(&g_l2h[c0 * 64 + 32 + lane]));
        float2 xa1 = unpack_f16x2(__ldg(&g_l2h[c1 * 64 + lane]));
        float2 xb1 = unpack_f16x2(__ldg(&g_l2h[c1 * 64 + 32 + lane]));
        float2 xa2 = unpack_f16x2(__ldg(&g_l2h[c2 * 64 + lane]));
        float2 xb2 = unpack_f16x2(__ldg(&g_l2h[c2 * 64 + 32 + lane]));
        float2 xa3 = unpack_f16x2(__ldg(&g_l2h[c3 * 64 + lane]));
        float2 xb3 = unpack_f16x2(__ldg(&g_l2h[c3 * 64 + 32 + lane]));
        fma2v(aa, v0.x, xa0); fma2v(ab, v0.y, xb0);
        fma2v(aa, v1.x, xa1); fma2v(ab, v1.y, xb1);
        fma2v(aa, v2.x, xa2); fma2v(ab, v2.y, xb2);
        fma2v(aa, v3.x, xa3); fma2v(ab, v3.y, xb3);
    }
    for (; s < s1; s++) {
        int c = __ldcs(&g_csr_col[s]);
        float2 v = __ldcs(&g_csr_vals2[s]);
        float2 xa = unpack_f16x2(__ldg(&g_l2h[c * 64 + lane]));
        float2 xb = unpack_f16x2(__ldg(&g_l2h[c * 64 + 32 + lane]));
        fma2v(aa, v.x, xa); fma2v(ab, v.y, xb);
    }
    const float2* E  = (const float2*)g_ego;
    const float2* L1 = (const float2*)g_l1;
    const float2* L2 = (const float2*)g_l2;
    float2 e  = E[warp * 32 + lane];
    float2 p1 = L1[warp * 64 + lane];
    float2 q1 = L1[warp * 64 + 32 + lane];
    float2 p2 = L2[warp * 64 + lane];
    float2 q2 = L2[warp * 64 + 32 + lane];
    float2* outA = (float2*)out;
    float2* outB = (float2*)out + NTOT * 32;
    __stcs(&outA[warp * 32 + lane],
           make_float2((e.x + p1.x + p2.x + aa.x) * 0.25f,
                       (e.y + p1.y + p2.y + aa.y) * 0.25f));
    __stcs(&outB[warp * 32 + lane],
           make_float2((e.x + q1.x + q2.x + ab.x) * 0.25f,
                       (e.y + q1.y + q2.y + ab.y) * 0.25f));
}

// ------------------------------------------------------------------
// 8) gate mean
// ------------------------------------------------------------------
__global__ void k_final(float* __restrict__ out) {
    out[2 * NTOT * DD] = (float)(g_gate_sum / (double)SS);
}

extern "C" void kernel_launch(void* const* d_in, const int* in_sizes, int n_in,
                              void* d_out, int out_size) {
    const float* user = (const float*)d_in[0];
    const float* item = (const float*)d_in[1];
    const int*   rows = (const int*)d_in[2];
    const int*   cols = (const int*)d_in[3];
    const float* vals = (const float*)d_in[4];
    const int*   sidx = (const int*)d_in[5];
    const float* eps  = (const float*)d_in[6];
    const float* W1   = (const float*)d_in[7];
    const float* b1   = (const float*)d_in[8];
    const float* W2   = (const float*)d_in[9];
    const float* b2   = (const float*)d_in[10];
    float* out = (float*)d_out;

    static int smem_set = 0;
    if (!smem_set) {
        cudaFuncSetAttribute(k_gate_mma,
                             cudaFuncAttributeMaxDynamicSharedMemorySize, GATE_DYN);
        smem_set = 1;
    }

    const int TB = 256;
    k_init_edges<<<(EE + TB - 1) / TB, TB>>>(vals, W1);
    k_prep<<<(NTOT * DD + TB - 1) / TB, TB>>>(user, item, rows, sidx);
    k_scan1<<<SCAN_B, 256>>>();
    k_gate_mma<<<SS / TE, 256, GATE_DYN>>>(rows, cols, vals, sidx, eps, b1, W2, b2);
    k_scan2<<<1, 1024>>>();
    k_scan3<<<SCAN_B, 256>>>();
    k_fill<<<(EE + TB - 1) / TB, TB>>>(rows, cols, vals);

    const int SPMM_BLOCKS = (NTOT * 32 + TB - 1) / TB;
    k_spmm_l1<<<SPMM_BLOCKS, TB>>>();
    k_spmm_l2<<<SPMM_BLOCKS, TB>>>();
    k_spmm_l3<<<SPMM_BLOCKS, TB>>>(out);

    k_final<<<1, 1>>>(out);
}

// round 12
// speedup vs baseline: 1.5811x; 1.1617x over previous
#include <cuda_runtime.h>
#include <cuda_fp16.h>
#include <math.h>
#include <cstdint>

#define NU 100000
#define NTOT 150000
#define DD 64
#define EE 1250000
#define SS 400000
#define TAU 0.2f
#define EDGE_BIAS 0.5f
#define SCAN_B 586   // ceil(NTOT/256)

typedef unsigned long long ull;

// ---- static scratch (no allocations allowed) ----
__device__ float    g_ego[NTOT * DD];      // fp32 ego (38.4 MB)
__device__ uint32_t g_ego_h[NTOT * 32];    // ego packed fp16x2 (19.2 MB)
__device__ uint32_t g_l1h[NTOT * 64];      // l1 interleaved fp16x2 (38.4 MB)
__device__ uint32_t g_l2h[NTOT * 64];      // l2 interleaved fp16x2
__device__ float    g_masked[EE];
__device__ uint2    g_csr8[EE];            // {col, f16x2(val, mval)} (10 MB)
__device__ int      g_counts[NTOT];
__device__ int      g_fillpos[NTOT];
__device__ int      g_rowptr[NTOT + 1];
__device__ int      g_bsum[1024];
__device__ int      g_lastS[EE];
__device__ uint32_t g_w1h[64 * 64];        // W1 packed fp16x2
__device__ double   g_gate_sum;

// ================= helpers =================
__device__ __forceinline__ uint32_t smem_u32(const void* p) {
    uint32_t a;
    asm("{ .reg .u64 t; cvta.to.shared.u64 t, %1; cvt.u32.u64 %0, t; }" : "=r"(a) : "l"(p));
    return a;
}
__device__ __forceinline__ uint32_t pack_f16x2(float lo, float hi) {
    uint32_t r;
    asm("cvt.rn.f16x2.f32 %0, %1, %2;" : "=r"(r) : "f"(hi), "f"(lo));
    return r;
}
__device__ __forceinline__ float2 unpack_f16x2(uint32_t u) {
    __half2 h = *reinterpret_cast<__half2*>(&u);
    return __half22float2(h);
}
__device__ __forceinline__ void ldsm_x4(uint32_t (&r)[4], uint32_t addr) {
    asm volatile("ldmatrix.sync.aligned.m8n8.x4.shared.b16 {%0,%1,%2,%3}, [%4];"
        : "=r"(r[0]), "=r"(r[1]), "=r"(r[2]), "=r"(r[3]) : "r"(addr));
}
__device__ __forceinline__ void ldsm_x4t(uint32_t (&r)[4], uint32_t addr) {
    asm volatile("ldmatrix.sync.aligned.m8n8.x4.trans.shared.b16 {%0,%1,%2,%3}, [%4];"
        : "=r"(r[0]), "=r"(r[1]), "=r"(r[2]), "=r"(r[3]) : "r"(addr));
}
__device__ __forceinline__ void mma_f16(float (&c)[4], const uint32_t (&a)[4],
                                        uint32_t b0, uint32_t b1) {
    asm volatile(
        "mma.sync.aligned.m16n8k16.row.col.f32.f16.f16.f32 "
        "{%0,%1,%2,%3}, {%4,%5,%6,%7}, {%8,%9}, {%0,%1,%2,%3};"
        : "+f"(c[0]), "+f"(c[1]), "+f"(c[2]), "+f"(c[3])
        : "r"(a[0]), "r"(a[1]), "r"(a[2]), "r"(a[3]), "r"(b0), "r"(b1));
}
__device__ __forceinline__ void fma2v(float2& a, float v, float2 x) {
    a.x = fmaf(v, x.x, a.x); a.y = fmaf(v, x.y, a.y);
}

// ------------------------------------------------------------------
// 1) per-edge init + pack W1 to fp16
// ------------------------------------------------------------------
__global__ void k_init_edges(const float* __restrict__ vals,
                             const float* __restrict__ W1) {
    int i = blockIdx.x * blockDim.x + threadIdx.x;
    if (i < EE) { g_masked[i] = vals[i]; g_lastS[i] = 0; }
    if (i < NTOT) { g_counts[i] = 0; g_fillpos[i] = 0; }
    if (i < 4096) {
        float v0 = W1[2 * i];
        float v1 = W1[2 * i + 1];
        g_w1h[i] = pack_f16x2(v0, v1);
    }
    if (i == 0) g_gate_sum = 0.0;
}

// ------------------------------------------------------------------
// 2) combined: ego copy (fp32 + packed fp16) + degree count + lastS
// ------------------------------------------------------------------
__global__ void k_prep(const float* __restrict__ user,
                       const float* __restrict__ item,
                       const int* __restrict__ rows,
                       const int* __restrict__ sidx) {
    int i = blockIdx.x * blockDim.x + threadIdx.x;
    if (i < NTOT * 32) {
        int j = 2 * i;
        float v0 = (j < NU * DD) ? user[j] : item[j - NU * DD];
        float v1 = (j + 1 < NU * DD) ? user[j + 1] : item[j + 1 - NU * DD];
        g_ego[j] = v0;
        g_ego[j + 1] = v1;
        g_ego_h[i] = pack_f16x2(v0, v1);
    }
    if (i < EE) atomicAdd(&g_counts[rows[i]], 1);
    if (i < SS) atomicMax(&g_lastS[sidx[i]], i);
}

// ------------------------------------------------------------------
// 3) gate MLP via fp16 mma.sync (proven, ~85us)
// ------------------------------------------------------------------
#define TE 128
#define A_STRIDE 136
#define B_STRIDE 72
#define A_TILE_B (128 * A_STRIDE * 2)
#define B_TILE_B (128 * B_STRIDE * 2)
#define GATE_DYN (A_TILE_B + B_TILE_B)

__global__ void __launch_bounds__(256)
k_gate_mma(const int* __restrict__ rows, const int* __restrict__ cols,
           const float* __restrict__ vals, const int* __restrict__ sidx,
           const float* __restrict__ eps,
           const float* __restrict__ b1,
           const float* __restrict__ W2, const float* __restrict__ b2) {
    extern __shared__ char dsm[];
    const uint32_t A0 = smem_u32(dsm);
    const uint32_t B0 = A0 + A_TILE_B;

    __shared__ float  b1s[64], W2s[64];
    __shared__ int    eidx[TE];
    __shared__ double gpart[8];

    const int tid  = threadIdx.x;
    const int wid  = tid >> 5;
    const int lane = tid & 31;
    const int base = blockIdx.x * TE;

    if (tid < 64) { b1s[tid] = b1[tid]; W2s[tid] = W2[tid]; }

    {
        const uint4* src = (const uint4*)g_w1h;
        for (int i = tid; i < 1024; i += 256) {
            int k = i >> 3, c4 = (i & 7) * 4;
            uint4 v = __ldg(&src[i]);
            *(uint4*)(dsm + A_TILE_B + (uint32_t)(k * B_STRIDE + 2 * c4) * 2u) = v;
        }
    }
    {
        int e = tid >> 1, p = tid & 1;
        int s = base + e;
        int idx = __ldg(&sidx[s]);
        if (p == 0) eidx[e] = idx;
        int node = p ? __ldg(&cols[idx]) : __ldg(&rows[idx]);
        const uint4* src = (const uint4*)(g_ego_h + node * 32);
        uint32_t rowoff = (uint32_t)(e * A_STRIDE + p * DD) * 2u;
#pragma unroll
        for (int j = 0; j < 8; j++) {
            uint4 v = __ldg(&src[j]);
            *(uint4*)(dsm + rowoff + (uint32_t)j * 16u) = v;
        }
    }
    __syncthreads();

    float C[8][4];
#pragma unroll
    for (int n = 0; n < 8; n++)
#pragma unroll
        for (int q = 0; q < 4; q++) C[n][q] = 0.f;

    const uint32_t a_lane_off =
        (uint32_t)((wid * 16 + (lane & 15)) * A_STRIDE + (lane >> 4) * 8) * 2u;
    const int bg  = lane >> 3;
    const int br  = lane & 7;
    const int b_krow_off = (bg & 1) * 8 + br;
    const int b_ncol_off = (bg >> 1) * 8;

#pragma unroll
    for (int k = 0; k < 8; k++) {
        uint32_t a[4];
        ldsm_x4(a, A0 + a_lane_off + (uint32_t)(k * 16 * 2));
        uint32_t b_base = B0 +
            (uint32_t)((k * 16 + b_krow_off) * B_STRIDE + b_ncol_off) * 2u;
#pragma unroll
        for (int nb = 0; nb < 4; nb++) {
            uint32_t b[4];
            ldsm_x4t(b, b_base + (uint32_t)(nb * 16 * 2));
            mma_f16(C[2 * nb],     a, b[0], b[1]);
            mma_f16(C[2 * nb + 1], a, b[2], b[3]);
        }
    }

    const int qr = lane >> 2;
    const int qc = (lane & 3) * 2;
    float pl = 0.f, ph = 0.f;
#pragma unroll
    for (int n = 0; n < 8; n++) {
        int c0 = n * 8 + qc, c1 = c0 + 1;
        pl += fmaxf(C[n][0] + b1s[c0], 0.f) * W2s[c0]
            + fmaxf(C[n][1] + b1s[c1], 0.f) * W2s[c1];
        ph += fmaxf(C[n][2] + b1s[c0], 0.f) * W2s[c0]
            + fmaxf(C[n][3] + b1s[c1], 0.f) * W2s[c1];
    }
    pl += __shfl_xor_sync(0xffffffffu, pl, 1);
    pl += __shfl_xor_sync(0xffffffffu, pl, 2);
    ph += __shfl_xor_sync(0xffffffffu, ph, 1);
    ph += __shfl_xor_sync(0xffffffffu, ph, 2);

    double gsum = 0.0;
    if ((lane & 3) == 0) {
        float b2v = __ldg(b2);
        float logit[2] = {pl + b2v, ph + b2v};
#pragma unroll
        for (int h = 0; h < 2; h++) {
            int e = wid * 16 + qr + h * 8;
            int s = base + e;
            float ee = __ldg(&eps[s]) * (1.f - 2e-6f) + 1e-6f;
            float gumbel = logf(ee) - log1pf(-ee);
            float gate = 1.f / (1.f + expf(-(logit[h] + gumbel) / TAU)) + EDGE_BIAS;
            gsum += (double)gate;
            int idx = eidx[e];
            if (g_lastS[idx] == s) g_masked[idx] = vals[idx] * gate;
        }
    }
#pragma unroll
    for (int off = 16; off; off >>= 1)
        gsum += __shfl_xor_sync(0xffffffffu, gsum, off);
    if (lane == 0) gpart[wid] = gsum;
    __syncthreads();
    if (tid == 0) {
        double t = 0.0;
#pragma unroll
        for (int i = 0; i < 8; i++) t += gpart[i];
        atomicAdd(&g_gate_sum, t);
    }
}

// ------------------------------------------------------------------
// 4) CSR scan (3-phase) + fill (packed 8B record)
// ------------------------------------------------------------------
__global__ void k_scan1() {
    __shared__ int sh[256];
    int i = blockIdx.x * 256 + threadIdx.x;
    int v = (i < NTOT) ? g_counts[i] : 0;
    sh[threadIdx.x] = v;
    __syncthreads();
    for (int off = 128; off; off >>= 1) {
        if (threadIdx.x < off) sh[threadIdx.x] += sh[threadIdx.x + off];
        __syncthreads();
    }
    if (threadIdx.x == 0) g_bsum[blockIdx.x] = sh[0];
}

__global__ void k_scan2() {
    __shared__ int sh[1024];
    int t = threadIdx.x;
    int v = (t < SCAN_B) ? g_bsum[t] : 0;
    sh[t] = v;
    __syncthreads();
    for (int off = 1; off < 1024; off <<= 1) {
        int u = (t >= off) ? sh[t - off] : 0;
        __syncthreads();
        sh[t] += u;
        __syncthreads();
    }
    if (t < SCAN_B) g_bsum[t] = sh[t] - v;  // exclusive
}

__global__ void k_scan3() {
    __shared__ int sh[256];
    int i = blockIdx.x * 256 + threadIdx.x;
    int v = (i < NTOT) ? g_counts[i] : 0;
    sh[threadIdx.x] = v;
    __syncthreads();
    for (int off = 1; off < 256; off <<= 1) {
        int u = (threadIdx.x >= off) ? sh[threadIdx.x - off] : 0;
        __syncthreads();
        sh[threadIdx.x] += u;
        __syncthreads();
    }
    if (i < NTOT) g_rowptr[i] = g_bsum[blockIdx.x] + sh[threadIdx.x] - v;
    if (i == 0) g_rowptr[NTOT] = EE;
}

__global__ void k_fill(const int* __restrict__ rows, const int* __restrict__ cols,
                       const float* __restrict__ vals) {
    int e = blockIdx.x * blockDim.x + threadIdx.x;
    if (e >= EE) return;
    int r = rows[e];
    int slot = g_rowptr[r] + atomicAdd(&g_fillpos[r], 1);
    uint2 rec;
    rec.x = (uint32_t)cols[e];
    rec.y = pack_f16x2(vals[e], g_masked[e]);
    g_csr8[slot] = rec;
}

// ------------------------------------------------------------------
// 5) SPMM layer 1: fp16 ego gather -> fp16 l1 mirror only
// ------------------------------------------------------------------
__global__ void k_spmm_l1() {
    int warp = (blockIdx.x * blockDim.x + threadIdx.x) >> 5;
    int lane = threadIdx.x & 31;
    if (warp >= NTOT) return;
    int s0 = __ldg(&g_rowptr[warp]);
    int s1 = __ldg(&g_rowptr[warp + 1]);
    float2 aa = make_float2(0.f, 0.f), ab = make_float2(0.f, 0.f);
    int s = s0;
    for (; s + 4 <= s1; s += 4) {
        uint2 r0 = __ldcs(&g_csr8[s]),     r1 = __ldcs(&g_csr8[s + 1]);
        uint2 r2 = __ldcs(&g_csr8[s + 2]), r3 = __ldcs(&g_csr8[s + 3]);
        float2 v0 = unpack_f16x2(r0.y), v1 = unpack_f16x2(r1.y);
        float2 v2 = unpack_f16x2(r2.y), v3 = unpack_f16x2(r3.y);
        float2 x0 = unpack_f16x2(__ldg(&g_ego_h[r0.x * 32 + lane]));
        float2 x1 = unpack_f16x2(__ldg(&g_ego_h[r1.x * 32 + lane]));
        float2 x2 = unpack_f16x2(__ldg(&g_ego_h[r2.x * 32 + lane]));
        float2 x3 = unpack_f16x2(__ldg(&g_ego_h[r3.x * 32 + lane]));
        fma2v(aa, v0.x, x0); fma2v(ab, v0.y, x0);
        fma2v(aa, v1.x, x1); fma2v(ab, v1.y, x1);
        fma2v(aa, v2.x, x2); fma2v(ab, v2.y, x2);
        fma2v(aa, v3.x, x3); fma2v(ab, v3.y, x3);
    }
    for (; s < s1; s++) {
        uint2 r = __ldcs(&g_csr8[s]);
        float2 v = unpack_f16x2(r.y);
        float2 x = unpack_f16x2(__ldg(&g_ego_h[r.x * 32 + lane]));
        fma2v(aa, v.x, x); fma2v(ab, v.y, x);
    }
    __stcs(&g_l1h[warp * 64 + lane], pack_f16x2(aa.x, aa.y));
    __stcs(&g_l1h[warp * 64 + 32 + lane], pack_f16x2(ab.x, ab.y));
}

// ------------------------------------------------------------------
// 6) SPMM layer 2: fp16 l1 gather -> fp16 l2 mirror only
// ------------------------------------------------------------------
__global__ void k_spmm_l2() {
    int warp = (blockIdx.x * blockDim.x + threadIdx.x) >> 5;
    int lane = threadIdx.x & 31;
    if (warp >= NTOT) return;
    int s0 = __ldg(&g_rowptr[warp]);
    int s1 = __ldg(&g_rowptr[warp + 1]);
    float2 aa = make_float2(0.f, 0.f), ab = make_float2(0.f, 0.f);
    int s = s0;
    for (; s + 4 <= s1; s += 4) {
        uint2 r0 = __ldcs(&g_csr8[s]),     r1 = __ldcs(&g_csr8[s + 1]);
        uint2 r2 = __ldcs(&g_csr8[s + 2]), r3 = __ldcs(&g_csr8[s + 3]);
        float2 v0 = unpack_f16x2(r0.y), v1 = unpack_f16x2(r1.y);
        float2 v2 = unpack_f16x2(r2.y), v3 = unpack_f16x2(r3.y);
        float2 xa0 = unpack_f16x2(__ldg(&g_l1h[r0.x * 64 + lane]));
        float2 xb0 = unpack_f16x2(__ldg(&g_l1h[r0.x * 64 + 32 + lane]));
        float2 xa1 = unpack_f16x2(__ldg(&g_l1h[r1.x * 64 + lane]));
        float2 xb1 = unpack_f16x2(__ldg(&g_l1h[r1.x * 64 + 32 + lane]));
        float2 xa2 = unpack_f16x2(__ldg(&g_l1h[r2.x * 64 + lane]));
        float2 xb2 = unpack_f16x2(__ldg(&g_l1h[r2.x * 64 + 32 + lane]));
        float2 xa3 = unpack_f16x2(__ldg(&g_l1h[r3.x * 64 + lane]));
        float2 xb3 = unpack_f16x2(__ldg(&g_l1h[r3.x * 64 + 32 + lane]));
        fma2v(aa, v0.x, xa0); fma2v(ab, v0.y, xb0);
        fma2v(aa, v1.x, xa1); fma2v(ab, v1.y, xb1);
        fma2v(aa, v2.x, xa2); fma2v(ab, v2.y, xb2);
        fma2v(aa, v3.x, xa3); fma2v(ab, v3.y, xb3);
    }
    for (; s < s1; s++) {
        uint2 r = __ldcs(&g_csr8[s]);
        float2 v = unpack_f16x2(r.y);
        float2 xa = unpack_f16x2(__ldg(&g_l1h[r.x * 64 + lane]));
        float2 xb = unpack_f16x2(__ldg(&g_l1h[r.x * 64 + 32 + lane]));
        fma2v(aa, v.x, xa); fma2v(ab, v.y, xb);
    }
    __stcs(&g_l2h[warp * 64 + lane], pack_f16x2(aa.x, aa.y));
    __stcs(&g_l2h[warp * 64 + 32 + lane], pack_f16x2(ab.x, ab.y));
}

// ------------------------------------------------------------------
// 7) SPMM layer 3: fp16 l2 gather + fused mean (ego fp32, l1/l2 fp16)
// ------------------------------------------------------------------
__global__ void k_spmm_l3(float* __restrict__ out) {
    int warp = (blockIdx.x * blockDim.x + threadIdx.x) >> 5;
    int lane = threadIdx.x & 31;
    if (warp >= NTOT) return;
    int s0 = __ldg(&g_rowptr[warp]);
    int s1 = __ldg(&g_rowptr[warp + 1]);
    float2 aa = make_float2(0.f, 0.f), ab = make_float2(0.f, 0.f);
    int s = s0;
    for (; s + 4 <= s1; s += 4) {
        uint2 r0 = __ldcs(&g_csr8[s]),     r1 = __ldcs(&g_csr8[s + 1]);
        uint2 r2 = __ldcs(&g_csr8[s + 2]), r3 = __ldcs(&g_csr8[s + 3]);
        float2 v0 = unpack_f16x2(r0.y), v1 = unpack_f16x2(r1.y);
        float2 v2 = unpack_f16x2(r2.y), v3 = unpack_f16x2(r3.y);
        float2 xa0 = unpack_f16x2(__ldg(&g_l2h[r0.x * 64 + lane]));
        float2 xb0 = unpack_f16x2(__ldg(&g_l2h[r0.x * 64 + 32 + lane]));
        float2 xa1 = unpack_f16x2(__ldg(&g_l2h[r1.x * 64 + lane]));
        float2 xb1 = unpack_f16x2(__ldg(&g_l2h[r1.x * 64 + 32 + lane]));
        float2 xa2 = unpack_f16x2(__ldg(&g_l2h[r2.x * 64 + lane]));
        float2 xb2 = unpack_f16x2(__ldg(&g_l2h[r2.x * 64 + 32 + lane]));
        float2 xa3 = unpack_f16x2(__ldg(&g_l2h[r3.x * 64 + lane]));
        float2 xb3 = unpack_f16x2(__ldg(&g_l2h[r3.x * 64 + 32 + lane]));
        fma2v(aa, v0.x, xa0); fma2v(ab, v0.y, xb0);
        fma2v(aa, v1.x, xa1); fma2v(ab, v1.y, xb1);
        fma2v(aa, v2.x, xa2); fma2v(ab, v2.y, xb2);
        fma2v(aa, v3.x, xa3); fma2v(ab, v3.y, xb3);
    }
    for (; s < s1; s++) {
        uint2 r = __ldcs(&g_csr8[s]);
        float2 v = unpack_f16x2(r.y);
        float2 xa = unpack_f16x2(__ldg(&g_l2h[r.x * 64 + lane]));
        float2 xb = unpack_f16x2(__ldg(&g_l2h[r.x * 64 + 32 + lane]));
        fma2v(aa, v.x, xa); fma2v(ab, v.y, xb);
    }
    const float2* E = (const float2*)g_ego;
    float2 e  = E[warp * 32 + lane];
    float2 p1 = unpack_f16x2(__ldg(&g_l1h[warp * 64 + lane]));
    float2 q1 = unpack_f16x2(__ldg(&g_l1h[warp * 64 + 32 + lane]));
    float2 p2 = unpack_f16x2(__ldg(&g_l2h[warp * 64 + lane]));
    float2 q2 = unpack_f16x2(__ldg(&g_l2h[warp * 64 + 32 + lane]));
    float2* outA = (float2*)out;
    float2* outB = (float2*)out + NTOT * 32;
    __stcs(&outA[warp * 32 + lane],
           make_float2((e.x + p1.x + p2.x + aa.x) * 0.25f,
                       (e.y + p1.y + p2.y + aa.y) * 0.25f));
    __stcs(&outB[warp * 32 + lane],
           make_float2((e.x + q1.x + q2.x + ab.x) * 0.25f,
                       (e.y + q1.y + q2.y + ab.y) * 0.25f));
}

// ------------------------------------------------------------------
// 8) gate mean
// ------------------------------------------------------------------
__global__ void k_final(float* __restrict__ out) {
    out[2 * NTOT * DD] = (float)(g_gate_sum / (double)SS);
}

extern "C" void kernel_launch(void* const* d_in, const int* in_sizes, int n_in,
                              void* d_out, int out_size) {
    const float* user = (const float*)d_in[0];
    const float* item = (const float*)d_in[1];
    const int*   rows = (const int*)d_in[2];
    const int*   cols = (const int*)d_in[3];
    const float* vals = (const float*)d_in[4];
    const int*   sidx = (const int*)d_in[5];
    const float* eps  = (const float*)d_in[6];
    const float* W1   = (const float*)d_in[7];
    const float* b1   = (const float*)d_in[8];
    const float* W2   = (const float*)d_in[9];
    const float* b2   = (const float*)d_in[10];
    float* out = (float*)d_out;

    static int smem_set = 0;
    if (!smem_set) {
        cudaFuncSetAttribute(k_gate_mma,
                             cudaFuncAttributeMaxDynamicSharedMemorySize, GATE_DYN);
        smem_set = 1;
    }

    const int TB = 256;
    k_init_edges<<<(EE + TB - 1) / TB, TB>>>(vals, W1);
    k_prep<<<(NTOT * DD + TB - 1) / TB, TB>>>(user, item, rows, sidx);
    k_scan1<<<SCAN_B, 256>>>();
    k_gate_mma<<<SS / TE, 256, GATE_DYN>>>(rows, cols, vals, sidx, eps, b1, W2, b2);
    k_scan2<<<1, 1024>>>();
    k_scan3<<<SCAN_B, 256>>>();
    k_fill<<<(EE + TB - 1) / TB, TB>>>(rows, cols, vals);

    const int SPMM_BLOCKS = (NTOT * 32 + TB - 1) / TB;
    k_spmm_l1<<<SPMM_BLOCKS, TB>>>();
    k_spmm_l2<<<SPMM_BLOCKS, TB>>>();
    k_spmm_l3<<<SPMM_BLOCKS, TB>>>(out);

    k_final<<<1, 1>>>(out);
}

// round 13
// speedup vs baseline: 1.6427x; 1.0389x over previous
#include <cuda_runtime.h>
#include <cuda_fp16.h>
#include <math.h>
#include <cstdint>

#define NU 100000
#define NTOT 150000
#define DD 64
#define EE 1250000
#define SS 400000
#define TAU 0.2f
#define EDGE_BIAS 0.5f
#define SCAN_B 586   // ceil(NTOT/256)

typedef unsigned long long ull;

// ---- static scratch (no allocations allowed) ----
__device__ float    g_ego[NTOT * DD];      // fp32 ego
__device__ uint32_t g_ego_h[NTOT * 32];    // ego packed fp16x2
__device__ uint2    g_l1p[NTOT * 32];      // l1 paired {orig_f16x2, masked_f16x2}
__device__ uint2    g_l2p[NTOT * 32];      // l2 paired
__device__ float    g_masked[EE];
__device__ uint2    g_csr8[EE];            // {col, f16x2(val, mval)}
__device__ int      g_counts[NTOT];
__device__ int      g_fillpos[NTOT];
__device__ int      g_rowptr[NTOT + 1];
__device__ int      g_bsum[1024];
__device__ int      g_lastS[EE];
__device__ uint32_t g_w1h[64 * 64];        // W1 packed fp16x2
__device__ double   g_gate_sum;

// ================= helpers =================
__device__ __forceinline__ uint32_t smem_u32(const void* p) {
    uint32_t a;
    asm("{ .reg .u64 t; cvta.to.shared.u64 t, %1; cvt.u32.u64 %0, t; }" : "=r"(a) : "l"(p));
    return a;
}
__device__ __forceinline__ uint32_t pack_f16x2(float lo, float hi) {
    uint32_t r;
    asm("cvt.rn.f16x2.f32 %0, %1, %2;" : "=r"(r) : "f"(hi), "f"(lo));
    return r;
}
__device__ __forceinline__ float2 unpack_f16x2(uint32_t u) {
    __half2 h = *reinterpret_cast<__half2*>(&u);
    return __half22float2(h);
}
__device__ __forceinline__ void cp_async16(uint32_t dst, const void* src) {
    asm volatile("cp.async.ca.shared.global [%0], [%1], 16;"
                 :: "r"(dst), "l"(src) : "memory");
}
__device__ __forceinline__ void cp_async_wait_all() {
    asm volatile("cp.async.commit_group;" ::: "memory");
    asm volatile("cp.async.wait_group 0;" ::: "memory");
}
__device__ __forceinline__ void ldsm_x4(uint32_t (&r)[4], uint32_t addr) {
    asm volatile("ldmatrix.sync.aligned.m8n8.x4.shared.b16 {%0,%1,%2,%3}, [%4];"
        : "=r"(r[0]), "=r"(r[1]), "=r"(r[2]), "=r"(r[3]) : "r"(addr));
}
__device__ __forceinline__ void ldsm_x4t(uint32_t (&r)[4], uint32_t addr) {
    asm volatile("ldmatrix.sync.aligned.m8n8.x4.trans.shared.b16 {%0,%1,%2,%3}, [%4];"
        : "=r"(r[0]), "=r"(r[1]), "=r"(r[2]), "=r"(r[3]) : "r"(addr));
}
__device__ __forceinline__ void mma_f16(float (&c)[4], const uint32_t (&a)[4],
                                        uint32_t b0, uint32_t b1) {
    asm volatile(
        "mma.sync.aligned.m16n8k16.row.col.f32.f16.f16.f32 "
        "{%0,%1,%2,%3}, {%4,%5,%6,%7}, {%8,%9}, {%0,%1,%2,%3};"
        : "+f"(c[0]), "+f"(c[1]), "+f"(c[2]), "+f"(c[3])
        : "r"(a[0]), "r"(a[1]), "r"(a[2]), "r"(a[3]), "r"(b0), "r"(b1));
}
__device__ __forceinline__ void fma2v(float2& a, float v, float2 x) {
    a.x = fmaf(v, x.x, a.x); a.y = fmaf(v, x.y, a.y);
}

// ------------------------------------------------------------------
// 1) per-edge init + pack W1 to fp16
// ------------------------------------------------------------------
__global__ void k_init_edges(const float* __restrict__ vals,
                             const float* __restrict__ W1) {
    int i = blockIdx.x * blockDim.x + threadIdx.x;
    if (i < EE) { g_masked[i] = vals[i]; g_lastS[i] = 0; }
    if (i < NTOT) { g_counts[i] = 0; g_fillpos[i] = 0; }
    if (i < 4096) {
        float v0 = W1[2 * i];
        float v1 = W1[2 * i + 1];
        g_w1h[i] = pack_f16x2(v0, v1);
    }
    if (i == 0) g_gate_sum = 0.0;
}

// ------------------------------------------------------------------
// 2) combined: ego copy (fp32 + packed fp16) + degree count + lastS
// ------------------------------------------------------------------
__global__ void k_prep(const float* __restrict__ user,
                       const float* __restrict__ item,
                       const int* __restrict__ rows,
                       const int* __restrict__ sidx) {
    int i = blockIdx.x * blockDim.x + threadIdx.x;
    if (i < NTOT * 32) {
        int j = 2 * i;
        float v0 = (j < NU * DD) ? user[j] : item[j - NU * DD];
        float v1 = (j + 1 < NU * DD) ? user[j + 1] : item[j + 1 - NU * DD];
        g_ego[j] = v0;
        g_ego[j + 1] = v1;
        g_ego_h[i] = pack_f16x2(v0, v1);
    }
    if (i < EE) atomicAdd(&g_counts[rows[i]], 1);
    if (i < SS) atomicMax(&g_lastS[sidx[i]], i);
}

// ------------------------------------------------------------------
// 3) gate MLP via fp16 mma.sync, cp.async staging
// ------------------------------------------------------------------
#define TE 128
#define A_STRIDE 136
#define B_STRIDE 72
#define A_TILE_B (128 * A_STRIDE * 2)
#define B_TILE_B (128 * B_STRIDE * 2)
#define GATE_DYN (A_TILE_B + B_TILE_B)

__global__ void __launch_bounds__(256)
k_gate_mma(const int* __restrict__ rows, const int* __restrict__ cols,
           const float* __restrict__ vals, const int* __restrict__ sidx,
           const float* __restrict__ eps,
           const float* __restrict__ b1,
           const float* __restrict__ W2, const float* __restrict__ b2) {
    extern __shared__ char dsm[];
    const uint32_t A0 = smem_u32(dsm);
    const uint32_t B0 = A0 + A_TILE_B;

    __shared__ float  b1s[64], W2s[64];
    __shared__ int    eidx[TE];
    __shared__ double gpart[8];

    const int tid  = threadIdx.x;
    const int wid  = tid >> 5;
    const int lane = tid & 31;
    const int base = blockIdx.x * TE;

    if (tid < 64) { b1s[tid] = b1[tid]; W2s[tid] = W2[tid]; }

    // ---- stage B via cp.async: 1024 x 16B ----
    {
        const uint4* src = (const uint4*)g_w1h;
        for (int i = tid; i < 1024; i += 256) {
            int k = i >> 3, c4 = (i & 7) * 4;
            cp_async16(B0 + (uint32_t)(k * B_STRIDE + 2 * c4) * 2u, src + i);
        }
    }
    // ---- stage A via cp.async: 2 threads/edge, 8 x 16B each ----
    {
        int e = tid >> 1, p = tid & 1;
        int s = base + e;
        int idx = __ldg(&sidx[s]);
        if (p == 0) eidx[e] = idx;
        int node = p ? __ldg(&cols[idx]) : __ldg(&rows[idx]);
        const uint4* src = (const uint4*)(g_ego_h + node * 32);
        uint32_t rowoff = A0 + (uint32_t)(e * A_STRIDE + p * DD) * 2u;
#pragma unroll
        for (int j = 0; j < 8; j++)
            cp_async16(rowoff + (uint32_t)j * 16u, src + j);
    }
    cp_async_wait_all();
    __syncthreads();

    float C[8][4];
#pragma unroll
    for (int n = 0; n < 8; n++)
#pragma unroll
        for (int q = 0; q < 4; q++) C[n][q] = 0.f;

    const uint32_t a_lane_off =
        (uint32_t)((wid * 16 + (lane & 15)) * A_STRIDE + (lane >> 4) * 8) * 2u;
    const int bg  = lane >> 3;
    const int br  = lane & 7;
    const int b_krow_off = (bg & 1) * 8 + br;
    const int b_ncol_off = (bg >> 1) * 8;

#pragma unroll
    for (int k = 0; k < 8; k++) {
        uint32_t a[4];
        ldsm_x4(a, A0 + a_lane_off + (uint32_t)(k * 16 * 2));
        uint32_t b_base = B0 +
            (uint32_t)((k * 16 + b_krow_off) * B_STRIDE + b_ncol_off) * 2u;
#pragma unroll
        for (int nb = 0; nb < 4; nb++) {
            uint32_t b[4];
            ldsm_x4t(b, b_base + (uint32_t)(nb * 16 * 2));
            mma_f16(C[2 * nb],     a, b[0], b[1]);
            mma_f16(C[2 * nb + 1], a, b[2], b[3]);
        }
    }

    const int qr = lane >> 2;
    const int qc = (lane & 3) * 2;
    float pl = 0.f, ph = 0.f;
#pragma unroll
    for (int n = 0; n < 8; n++) {
        int c0 = n * 8 + qc, c1 = c0 + 1;
        pl += fmaxf(C[n][0] + b1s[c0], 0.f) * W2s[c0]
            + fmaxf(C[n][1] + b1s[c1], 0.f) * W2s[c1];
        ph += fmaxf(C[n][2] + b1s[c0], 0.f) * W2s[c0]
            + fmaxf(C[n][3] + b1s[c1], 0.f) * W2s[c1];
    }
    pl += __shfl_xor_sync(0xffffffffu, pl, 1);
    pl += __shfl_xor_sync(0xffffffffu, pl, 2);
    ph += __shfl_xor_sync(0xffffffffu, ph, 1);
    ph += __shfl_xor_sync(0xffffffffu, ph, 2);

    double gsum = 0.0;
    if ((lane & 3) == 0) {
        float b2v = __ldg(b2);
        float logit[2] = {pl + b2v, ph + b2v};
#pragma unroll
        for (int h = 0; h < 2; h++) {
            int e = wid * 16 + qr + h * 8;
            int s = base + e;
            float ee = __ldg(&eps[s]) * (1.f - 2e-6f) + 1e-6f;
            float gumbel = logf(ee) - log1pf(-ee);
            float gate = 1.f / (1.f + expf(-(logit[h] + gumbel) / TAU)) + EDGE_BIAS;
            gsum += (double)gate;
            int idx = eidx[e];
            if (g_lastS[idx] == s) g_masked[idx] = vals[idx] * gate;
        }
    }
#pragma unroll
    for (int off = 16; off; off >>= 1)
        gsum += __shfl_xor_sync(0xffffffffu, gsum, off);
    if (lane == 0) gpart[wid] = gsum;
    __syncthreads();
    if (tid == 0) {
        double t = 0.0;
#pragma unroll
        for (int i = 0; i < 8; i++) t += gpart[i];
        atomicAdd(&g_gate_sum, t);
    }
}

// ------------------------------------------------------------------
// 4) CSR scan (3-phase) + fill (packed 8B record)
// ------------------------------------------------------------------
__global__ void k_scan1() {
    __shared__ int sh[256];
    int i = blockIdx.x * 256 + threadIdx.x;
    int v = (i < NTOT) ? g_counts[i] : 0;
    sh[threadIdx.x] = v;
    __syncthreads();
    for (int off = 128; off; off >>= 1) {
        if (threadIdx.x < off) sh[threadIdx.x] += sh[threadIdx.x + off];
        __syncthreads();
    }
    if (threadIdx.x == 0) g_bsum[blockIdx.x] = sh[0];
}

__global__ void k_scan2() {
    __shared__ int sh[1024];
    int t = threadIdx.x;
    int v = (t < SCAN_B) ? g_bsum[t] : 0;
    sh[t] = v;
    __syncthreads();
    for (int off = 1; off < 1024; off <<= 1) {
        int u = (t >= off) ? sh[t - off] : 0;
        __syncthreads();
        sh[t] += u;
        __syncthreads();
    }
    if (t < SCAN_B) g_bsum[t] = sh[t] - v;  // exclusive
}

__global__ void k_scan3() {
    __shared__ int sh[256];
    int i = blockIdx.x * 256 + threadIdx.x;
    int v = (i < NTOT) ? g_counts[i] : 0;
    sh[threadIdx.x] = v;
    __syncthreads();
    for (int off = 1; off < 256; off <<= 1) {
        int u = (threadIdx.x >= off) ? sh[threadIdx.x - off] : 0;
        __syncthreads();
        sh[threadIdx.x] += u;
        __syncthreads();
    }
    if (i < NTOT) g_rowptr[i] = g_bsum[blockIdx.x] + sh[threadIdx.x] - v;
    if (i == 0) g_rowptr[NTOT] = EE;
}

__global__ void k_fill(const int* __restrict__ rows, const int* __restrict__ cols,
                       const float* __restrict__ vals) {
    int e = blockIdx.x * blockDim.x + threadIdx.x;
    if (e >= EE) return;
    int r = rows[e];
    int slot = g_rowptr[r] + atomicAdd(&g_fillpos[r], 1);
    uint2 rec;
    rec.x = (uint32_t)cols[e];
    rec.y = pack_f16x2(vals[e], g_masked[e]);
    g_csr8[slot] = rec;
}

// ------------------------------------------------------------------
// 5) SPMM layer 1: fp16 ego gather -> paired fp16 l1
// ------------------------------------------------------------------
__global__ void k_spmm_l1() {
    int warp = (blockIdx.x * blockDim.x + threadIdx.x) >> 5;
    int lane = threadIdx.x & 31;
    if (warp >= NTOT) return;
    int s0 = __ldg(&g_rowptr[warp]);
    int s1 = __ldg(&g_rowptr[warp + 1]);
    float2 aa = make_float2(0.f, 0.f), ab = make_float2(0.f, 0.f);
    int s = s0;
    for (; s + 4 <= s1; s += 4) {
        uint2 r0 = __ldcs(&g_csr8[s]),     r1 = __ldcs(&g_csr8[s + 1]);
        uint2 r2 = __ldcs(&g_csr8[s + 2]), r3 = __ldcs(&g_csr8[s + 3]);
        float2 v0 = unpack_f16x2(r0.y), v1 = unpack_f16x2(r1.y);
        float2 v2 = unpack_f16x2(r2.y), v3 = unpack_f16x2(r3.y);
        float2 x0 = unpack_f16x2(__ldg(&g_ego_h[r0.x * 32 + lane]));
        float2 x1 = unpack_f16x2(__ldg(&g_ego_h[r1.x * 32 + lane]));
        float2 x2 = unpack_f16x2(__ldg(&g_ego_h[r2.x * 32 + lane]));
        float2 x3 = unpack_f16x2(__ldg(&g_ego_h[r3.x * 32 + lane]));
        fma2v(aa, v0.x, x0); fma2v(ab, v0.y, x0);
        fma2v(aa, v1.x, x1); fma2v(ab, v1.y, x1);
        fma2v(aa, v2.x, x2); fma2v(ab, v2.y, x2);
        fma2v(aa, v3.x, x3); fma2v(ab, v3.y, x3);
    }
    for (; s < s1; s++) {
        uint2 r = __ldcs(&g_csr8[s]);
        float2 v = unpack_f16x2(r.y);
        float2 x = unpack_f16x2(__ldg(&g_ego_h[r.x * 32 + lane]));
        fma2v(aa, v.x, x); fma2v(ab, v.y, x);
    }
    __stcs(&g_l1p[warp * 32 + lane],
           make_uint2(pack_f16x2(aa.x, aa.y), pack_f16x2(ab.x, ab.y)));
}

// ------------------------------------------------------------------
// 6) SPMM layer 2: paired fp16 l1 gather -> paired fp16 l2
// ------------------------------------------------------------------
__global__ void k_spmm_l2() {
    int warp = (blockIdx.x * blockDim.x + threadIdx.x) >> 5;
    int lane = threadIdx.x & 31;
    if (warp >= NTOT) return;
    int s0 = __ldg(&g_rowptr[warp]);
    int s1 = __ldg(&g_rowptr[warp + 1]);
    float2 aa = make_float2(0.f, 0.f), ab = make_float2(0.f, 0.f);
    int s = s0;
    for (; s + 4 <= s1; s += 4) {
        uint2 r0 = __ldcs(&g_csr8[s]),     r1 = __ldcs(&g_csr8[s + 1]);
        uint2 r2 = __ldcs(&g_csr8[s + 2]), r3 = __ldcs(&g_csr8[s + 3]);
        float2 v0 = unpack_f16x2(r0.y), v1 = unpack_f16x2(r1.y);
        float2 v2 = unpack_f16x2(r2.y), v3 = unpack_f16x2(r3.y);
        uint2 u0 = __ldg(&g_l1p[r0.x * 32 + lane]);
        uint2 u1 = __ldg(&g_l1p[r1.x * 32 + lane]);
        uint2 u2 = __ldg(&g_l1p[r2.x * 32 + lane]);
        uint2 u3 = __ldg(&g_l1p[r3.x * 32 + lane]);
        fma2v(aa, v0.x, unpack_f16x2(u0.x)); fma2v(ab, v0.y, unpack_f16x2(u0.y));
        fma2v(aa, v1.x, unpack_f16x2(u1.x)); fma2v(ab, v1.y, unpack_f16x2(u1.y));
        fma2v(aa, v2.x, unpack_f16x2(u2.x)); fma2v(ab, v2.y, unpack_f16x2(u2.y));
        fma2v(aa, v3.x, unpack_f16x2(u3.x)); fma2v(ab, v3.y, unpack_f16x2(u3.y));
    }
    for (; s < s1; s++) {
        uint2 r = __ldcs(&g_csr8[s]);
        float2 v = unpack_f16x2(r.y);
        uint2 u = __ldg(&g_l1p[r.x * 32 + lane]);
        fma2v(aa, v.x, unpack_f16x2(u.x)); fma2v(ab, v.y, unpack_f16x2(u.y));
    }
    __stcs(&g_l2p[warp * 32 + lane],
           make_uint2(pack_f16x2(aa.x, aa.y), pack_f16x2(ab.x, ab.y)));
}

// ------------------------------------------------------------------
// 7) SPMM layer 3: paired fp16 l2 gather + fused mean
// ------------------------------------------------------------------
__global__ void k_spmm_l3(float* __restrict__ out) {
    int warp = (blockIdx.x * blockDim.x + threadIdx.x) >> 5;
    int lane = threadIdx.x & 31;
    if (warp >= NTOT) return;
    int s0 = __ldg(&g_rowptr[warp]);
    int s1 = __ldg(&g_rowptr[warp + 1]);
    float2 aa = make_float2(0.f, 0.f), ab = make_float2(0.f, 0.f);
    int s = s0;
    for (; s + 4 <= s1; s += 4) {
        uint2 r0 = __ldcs(&g_csr8[s]),     r1 = __ldcs(&g_csr8[s + 1]);
        uint2 r2 = __ldcs(&g_csr8[s + 2]), r3 = __ldcs(&g_csr8[s + 3]);
        float2 v0 = unpack_f16x2(r0.y), v1 = unpack_f16x2(r1.y);
        float2 v2 = unpack_f16x2(r2.y), v3 = unpack_f16x2(r3.y);
        uint2 u0 = __ldg(&g_l2p[r0.x * 32 + lane]);
        uint2 u1 = __ldg(&g_l2p[r1.x * 32 + lane]);
        uint2 u2 = __ldg(&g_l2p[r2.x * 32 + lane]);
        uint2 u3 = __ldg(&g_l2p[r3.x * 32 + lane]);
        fma2v(aa, v0.x, unpack_f16x2(u0.x)); fma2v(ab, v0.y, unpack_f16x2(u0.y));
        fma2v(aa, v1.x, unpack_f16x2(u1.x)); fma2v(ab, v1.y, unpack_f16x2(u1.y));
        fma2v(aa, v2.x, unpack_f16x2(u2.x)); fma2v(ab, v2.y, unpack_f16x2(u2.y));
        fma2v(aa, v3.x, unpack_f16x2(u3.x)); fma2v(ab, v3.y, unpack_f16x2(u3.y));
    }
    for (; s < s1; s++) {
        uint2 r = __ldcs(&g_csr8[s]);
        float2 v = unpack_f16x2(r.y);
        uint2 u = __ldg(&g_l2p[r.x * 32 + lane]);
        fma2v(aa, v.x, unpack_f16x2(u.x)); fma2v(ab, v.y, unpack_f16x2(u.y));
    }
    const float2* E = (const float2*)g_ego;
    float2 e  = E[warp * 32 + lane];
    uint2 u1 = __ldg(&g_l1p[warp * 32 + lane]);
    uint2 u2 = __ldg(&g_l2p[warp * 32 + lane]);
    float2 p1 = unpack_f16x2(u1.x), q1 = unpack_f16x2(u1.y);
    float2 p2 = unpack_f16x2(u2.x), q2 = unpack_f16x2(u2.y);
    float2* outA = (float2*)out;
    float2* outB = (float2*)out + NTOT * 32;
    __stcs(&outA[warp * 32 + lane],
           make_float2((e.x + p1.x + p2.x + aa.x) * 0.25f,
                       (e.y + p1.y + p2.y + aa.y) * 0.25f));
    __stcs(&outB[warp * 32 + lane],
           make_float2((e.x + q1.x + q2.x + ab.x) * 0.25f,
                       (e.y + q1.y + q2.y + ab.y) * 0.25f));
}

// ------------------------------------------------------------------
// 8) gate mean
// ------------------------------------------------------------------
__global__ void k_final(float* __restrict__ out) {
    out[2 * NTOT * DD] = (float)(g_gate_sum / (double)SS);
}

extern "C" void kernel_launch(void* const* d_in, const int* in_sizes, int n_in,
                              void* d_out, int out_size) {
    const float* user = (const float*)d_in[0];
    const float* item = (const float*)d_in[1];
    const int*   rows = (const int*)d_in[2];
    const int*   cols = (const int*)d_in[3];
    const float* vals = (const float*)d_in[4];
    const int*   sidx = (const int*)d_in[5];
    const float* eps  = (const float*)d_in[6];
    const float* W1   = (const float*)d_in[7];
    const float* b1   = (const float*)d_in[8];
    const float* W2   = (const float*)d_in[9];
    const float* b2   = (const float*)d_in[10];
    float* out = (float*)d_out;

    static int smem_set = 0;
    if (!smem_set) {
        cudaFuncSetAttribute(k_gate_mma,
                             cudaFuncAttributeMaxDynamicSharedMemorySize, GATE_DYN);
        smem_set = 1;
    }

    const int TB = 256;
    k_init_edges<<<(EE + TB - 1) / TB, TB>>>(vals, W1);
    k_prep<<<(NTOT * DD + TB - 1) / TB, TB>>>(user, item, rows, sidx);
    k_scan1<<<SCAN_B, 256>>>();
    k_gate_mma<<<SS / TE, 256, GATE_DYN>>>(rows, cols, vals, sidx, eps, b1, W2, b2);
    k_scan2<<<1, 1024>>>();
    k_scan3<<<SCAN_B, 256>>>();
    k_fill<<<(EE + TB - 1) / TB, TB>>>(rows, cols, vals);

    const int SPMM_BLOCKS = (NTOT * 32 + TB - 1) / TB;
    k_spmm_l1<<<SPMM_BLOCKS, TB>>>();
    k_spmm_l2<<<SPMM_BLOCKS, TB>>>();
    k_spmm_l3<<<SPMM_BLOCKS, TB>>>(out);

    k_final<<<1, 1>>>(out);
}